// round 1
// baseline (speedup 1.0000x reference)
#include <cuda_runtime.h>
#include <cstdint>

// Problem constants
#define BB 64
#define SS 4096
#define HH 256
#define AA 128
#define NTOK (BB * SS)          // 262144 tokens

// ---------------- scratch (device globals; no allocation allowed) ----------
__device__ float g_scores[NTOK];                  // [B,S] pre-entmax scores
__device__ float g_partial[BB * 32 * HH];         // context partials

// ============================================================================
// Kernel 1: fused score MLP.
//   scores[tok] = b2 + sum_a tanh( sum_h X[tok,h]*W1[h,a] + b1[a] ) * W2[a]
// SGEMM tile: BM=128 tokens x BN=128 (all A), BK=16, 256 threads, 8x8 micro.
// ============================================================================
__global__ __launch_bounds__(256) void scores_kernel(
    const float* __restrict__ X,    // [NTOK, 256]
    const float* __restrict__ W1,   // [256, 128]
    const float* __restrict__ b1,   // [128]
    const float* __restrict__ W2,   // [128]
    const float* __restrict__ b2)   // [1]
{
    __shared__ float sX[16][128];   // [k][m]  (transposed X tile)
    __shared__ float sW[16][128];   // [k][n]

    const int tid = threadIdx.x;
    const int x = tid & 15;         // 0..15 -> N direction
    const int y = tid >> 4;         // 0..15 -> M direction
    const int tok0 = blockIdx.x * 128;

    const float* Xb = X + (size_t)tok0 * HH;

    float acc[8][8];
#pragma unroll
    for (int i = 0; i < 8; i++)
#pragma unroll
        for (int j = 0; j < 8; j++) acc[i][j] = 0.0f;

    // ---- load helpers (per 16-wide K tile) ----
    // X tile: 128 rows x 16 k  = 512 float4, 2 per thread (stored transposed)
    // W tile: 16 rows x 128 n  = 512 float4, 2 per thread
    const int xr0 = tid >> 2,        xq0 = (tid & 3) * 4;
    const int xr1 = (tid + 256) >> 2, xq1 = (tid & 3) * 4;
    const int wr0 = tid >> 5,        wq0 = (tid & 31) * 4;
    const int wr1 = (tid + 256) >> 5, wq1 = (tid & 31) * 4;

    float4 rx0, rx1, rw0, rw1;

    // prologue: tile 0
    rx0 = *(const float4*)(Xb + (size_t)xr0 * HH + xq0);
    rx1 = *(const float4*)(Xb + (size_t)xr1 * HH + xq1);
    rw0 = *(const float4*)(W1 + (size_t)wr0 * AA + wq0);
    rw1 = *(const float4*)(W1 + (size_t)wr1 * AA + wq1);

    sX[xq0 + 0][xr0] = rx0.x; sX[xq0 + 1][xr0] = rx0.y;
    sX[xq0 + 2][xr0] = rx0.z; sX[xq0 + 3][xr0] = rx0.w;
    sX[xq1 + 0][xr1] = rx1.x; sX[xq1 + 1][xr1] = rx1.y;
    sX[xq1 + 2][xr1] = rx1.z; sX[xq1 + 3][xr1] = rx1.w;
    *(float4*)&sW[wr0][wq0] = rw0;
    *(float4*)&sW[wr1][wq1] = rw1;
    __syncthreads();

    for (int kt = 0; kt < 16; kt++) {
        if (kt < 15) {
            const int k0 = (kt + 1) * 16;
            rx0 = *(const float4*)(Xb + (size_t)xr0 * HH + k0 + xq0);
            rx1 = *(const float4*)(Xb + (size_t)xr1 * HH + k0 + xq1);
            rw0 = *(const float4*)(W1 + (size_t)(k0 + wr0) * AA + wq0);
            rw1 = *(const float4*)(W1 + (size_t)(k0 + wr1) * AA + wq1);
        }
#pragma unroll
        for (int k = 0; k < 16; k++) {
            float a[8], bv[8];
#pragma unroll
            for (int i = 0; i < 8; i++) a[i] = sX[k][y * 8 + i];
#pragma unroll
            for (int j = 0; j < 8; j++) bv[j] = sW[k][x + 16 * j];
#pragma unroll
            for (int i = 0; i < 8; i++)
#pragma unroll
                for (int j = 0; j < 8; j++)
                    acc[i][j] = fmaf(a[i], bv[j], acc[i][j]);
        }
        __syncthreads();
        if (kt < 15) {
            sX[xq0 + 0][xr0] = rx0.x; sX[xq0 + 1][xr0] = rx0.y;
            sX[xq0 + 2][xr0] = rx0.z; sX[xq0 + 3][xr0] = rx0.w;
            sX[xq1 + 0][xr1] = rx1.x; sX[xq1 + 1][xr1] = rx1.y;
            sX[xq1 + 2][xr1] = rx1.z; sX[xq1 + 3][xr1] = rx1.w;
            *(float4*)&sW[wr0][wq0] = rw0;
            *(float4*)&sW[wr1][wq1] = rw1;
            __syncthreads();
        }
    }

    // ---- epilogue: tanh, *W2, reduce over A ----
    float bb1[8], w2v[8];
#pragma unroll
    for (int j = 0; j < 8; j++) {
        const int col = x + 16 * j;
        bb1[j] = b1[col];
        w2v[j] = W2[col];
    }
    const float b2v = b2[0];

#pragma unroll
    for (int i = 0; i < 8; i++) {
        float s = 0.0f;
#pragma unroll
        for (int j = 0; j < 8; j++)
            s += tanhf(acc[i][j] + bb1[j]) * w2v[j];
        // reduce across the 16 x-lanes (within half-warp)
        s += __shfl_xor_sync(0xffffffffu, s, 8);
        s += __shfl_xor_sync(0xffffffffu, s, 4);
        s += __shfl_xor_sync(0xffffffffu, s, 2);
        s += __shfl_xor_sync(0xffffffffu, s, 1);
        if (x == 0)
            g_scores[tok0 + y * 8 + i] = s + b2v;
    }
}

// ============================================================================
// Kernel 2: exact entmax-1.5 per batch row (S=4096). One block per row.
//   512 threads: bitonic sort + two cumulative sums + tau / k_star / weights.
// ============================================================================
__global__ __launch_bounds__(512) void entmax_kernel(float* __restrict__ weights)
{
    const int b = blockIdx.x;
    const int tid = threadIdx.x;

    __shared__ float srt[SS];     // holds -(z) for ascending sort  (16KB)
    __shared__ float tau[SS];     // tau per k                       (16KB)
    __shared__ float aux1[512], aux2[512];
    __shared__ float red[512];
    __shared__ float s_bcast[2];  // [0]=max, [1]=tau_star

    const float* sc = g_scores + (size_t)b * SS;

    // z = score/2 ; find max
    float m = -1e30f;
    for (int i = tid; i < SS; i += 512) {
        float v = 0.5f * sc[i];
        srt[i] = v;               // temporarily z/2
        m = fmaxf(m, v);
    }
    red[tid] = m;
    __syncthreads();
    for (int s = 256; s > 0; s >>= 1) {
        if (tid < s) red[tid] = fmaxf(red[tid], red[tid + s]);
        __syncthreads();
    }
    const float mx = red[0];
    __syncthreads();

    // srt = -(z - mx)  (>=0), sort ascending => zs[k] = -srt[k] descending
    for (int i = tid; i < SS; i += 512)
        srt[i] = mx - srt[i];
    __syncthreads();

    // bitonic ascending sort of srt[0..4095]
    for (int kk = 2; kk <= SS; kk <<= 1) {
        for (int jj = kk >> 1; jj > 0; jj >>= 1) {
            for (int i = tid; i < SS; i += 512) {
                const int l = i ^ jj;
                if (l > i) {
                    const float a = srt[i];
                    const float c = srt[l];
                    const bool up = ((i & kk) == 0);
                    if (up ? (a > c) : (a < c)) { srt[i] = c; srt[l] = a; }
                }
            }
            __syncthreads();
        }
    }

    // cumulative sums of zs and zs^2 (zs = -srt), 8 consecutive elems/thread
    const int base = tid * 8;
    float l1[8], l2[8];
    {
        float s1 = 0.0f, s2 = 0.0f;
#pragma unroll
        for (int j = 0; j < 8; j++) {
            const float v = -srt[base + j];
            s1 += v; s2 += v * v;
            l1[j] = s1; l2[j] = s2;
        }
        aux1[tid] = s1; aux2[tid] = s2;
    }
    __syncthreads();
    for (int off = 1; off < 512; off <<= 1) {
        float a1 = 0.0f, a2 = 0.0f;
        if (tid >= off) { a1 = aux1[tid - off]; a2 = aux2[tid - off]; }
        __syncthreads();
        aux1[tid] += a1; aux2[tid] += a2;
        __syncthreads();
    }
    const float off1 = aux1[tid] - l1[7];
    const float off2 = aux2[tid] - l2[7];

    // tau per k, count tau <= zs
    float cnt = 0.0f;
#pragma unroll
    for (int j = 0; j < 8; j++) {
        const int k = base + j;
        const float fk = (float)(k + 1);
        const float c1 = off1 + l1[j];
        const float c2 = off2 + l2[j];
        const float mean = c1 / fk;
        const float msq  = c2 / fk;
        const float ssv  = fk * (msq - mean * mean);
        const float delta = fmaxf((1.0f - ssv) / fk, 0.0f);
        const float t = mean - sqrtf(delta);
        tau[k] = t;
        const float zsk = -srt[k];
        if (t <= zsk) cnt += 1.0f;
    }
    red[tid] = cnt;
    __syncthreads();
    for (int s = 256; s > 0; s >>= 1) {
        if (tid < s) red[tid] += red[tid + s];
        __syncthreads();
    }
    if (tid == 0) {
        const int k_star = (int)(red[0] + 0.5f);
        s_bcast[1] = tau[k_star - 1];
    }
    __syncthreads();
    const float tau_star = s_bcast[1];

    // weights = relu(z - tau_star)^2  (z recomputed from gmem scores)
    float* wout = weights + (size_t)b * SS;
    for (int i = tid; i < SS; i += 512) {
        const float v = 0.5f * sc[i] - mx - tau_star;
        const float r = v > 0.0f ? v : 0.0f;
        wout[i] = r * r;
    }
}

// ============================================================================
// Kernel 3: context partials.  grid (B, 32), 256 threads (one per h).
//   Skips zero-weight rows (entmax output is sparse; branch is uniform).
// ============================================================================
__global__ __launch_bounds__(256) void ctx_partial_kernel(
    const float* __restrict__ X, const float* __restrict__ weights)
{
    const int b = blockIdx.x;
    const int c = blockIdx.y;
    const int h = threadIdx.x;

    __shared__ float ws[128];
    if (h < 128) ws[h] = weights[(size_t)b * SS + c * 128 + h];
    __syncthreads();

    const float* xb = X + ((size_t)b * SS + (size_t)c * 128) * HH;
    float acc = 0.0f;
#pragma unroll 2
    for (int s = 0; s < 128; s++) {
        const float w = ws[s];
        if (w != 0.0f)
            acc = fmaf(xb[(size_t)s * HH + h], w, acc);
    }
    g_partial[((size_t)b * 32 + c) * HH + h] = acc;
}

// Kernel 4: final reduce of 32 partials -> context [B, H]
__global__ __launch_bounds__(256) void ctx_reduce_kernel(float* __restrict__ ctx)
{
    const int b = blockIdx.x;
    const int h = threadIdx.x;
    float s = 0.0f;
#pragma unroll
    for (int c = 0; c < 32; c++)
        s += g_partial[((size_t)b * 32 + c) * HH + h];
    ctx[(size_t)b * HH + h] = s;
}

// ============================================================================
extern "C" void kernel_launch(void* const* d_in, const int* in_sizes, int n_in,
                              void* d_out, int out_size)
{
    const float* X  = (const float*)d_in[0];   // [64,4096,256]
    const float* W1 = (const float*)d_in[1];   // [256,128]
    const float* b1 = (const float*)d_in[2];   // [128]
    const float* W2 = (const float*)d_in[3];   // [128,1]
    const float* b2 = (const float*)d_in[4];   // [1]

    float* out = (float*)d_out;
    float* ctx = out;                 // [64,256]  (tuple elem 0)
    float* wts = out + BB * HH;       // [64,4096] (tuple elem 1)

    scores_kernel<<<NTOK / 128, 256>>>(X, W1, b1, W2, b2);
    entmax_kernel<<<BB, 512>>>(wts);
    ctx_partial_kernel<<<dim3(BB, 32), 256>>>(X, wts);
    ctx_reduce_kernel<<<BB, 256>>>(ctx);
}

// round 2
// speedup vs baseline: 1.0636x; 1.0636x over previous
#include <cuda_runtime.h>
#include <cstdint>

// Problem constants
#define BB 64
#define SS 4096
#define HH 256
#define AA 128
#define NTOK (BB * SS)          // 262144 tokens

// ---------------- scratch (device globals; no allocation allowed) ----------
__device__ float g_scores[NTOK];                  // [B,S] pre-entmax scores
__device__ float g_partial[BB * 32 * HH];         // context partials

// ---------------- packed fp32x2 helpers (sm_103a FFMA2) --------------------
__device__ __forceinline__ unsigned long long fma_f32x2(
    unsigned long long a, unsigned long long b, unsigned long long c)
{
    unsigned long long d;
    asm("fma.rn.f32x2 %0, %1, %2, %3;" : "=l"(d) : "l"(a), "l"(b), "l"(c));
    return d;
}
__device__ __forceinline__ unsigned long long dup_f32(float x)
{
    unsigned long long d;
    asm("mov.b64 %0, {%1, %1};" : "=l"(d) : "r"(__float_as_uint(x)));
    return d;
}
__device__ __forceinline__ void unpack_f32x2(unsigned long long v, float& lo, float& hi)
{
    unsigned int l, h;
    asm("mov.b64 {%0, %1}, %2;" : "=r"(l), "=r"(h) : "l"(v));
    lo = __uint_as_float(l);
    hi = __uint_as_float(h);
}

// ============================================================================
// Kernel 1: fused score MLP (FFMA2 inner loop).
//   scores[tok] = b2 + sum_a tanh( sum_h X[tok,h]*W1[h,a] + b1[a] ) * W2[a]
// Tile: BM=128 tokens x BN=128 (all A), BK=16, 256 threads.
// Thread micro-tile: 8 rows (y*8..y*8+7, as 4 packed row-pairs) x 8 cols
// (x*8..x*8+7).
// ============================================================================
__global__ __launch_bounds__(256) void scores_kernel(
    const float* __restrict__ X,    // [NTOK, 256]
    const float* __restrict__ W1,   // [256, 128]
    const float* __restrict__ b1,   // [128]
    const float* __restrict__ W2,   // [128]
    const float* __restrict__ b2)   // [1]
{
    __shared__ float sX[16][128];   // [k][m]  (transposed X tile)
    __shared__ float sW[16][128];   // [k][n]

    const int tid = threadIdx.x;
    const int x = tid & 15;         // 0..15 -> N direction (cols x*8..x*8+7)
    const int y = tid >> 4;         // 0..15 -> M direction (rows y*8..y*8+7)
    const int tok0 = blockIdx.x * 128;

    const float* Xb = X + (size_t)tok0 * HH;

    unsigned long long acc2[4][8];  // [row-pair][col], each packs rows (2p,2p+1)
#pragma unroll
    for (int p = 0; p < 4; p++)
#pragma unroll
        for (int j = 0; j < 8; j++) acc2[p][j] = 0ULL;

    // ---- load helpers (per 16-wide K tile) ----
    const int xr0 = tid >> 2,         xq0 = (tid & 3) * 4;
    const int xr1 = (tid + 256) >> 2, xq1 = (tid & 3) * 4;
    const int wr0 = tid >> 5,         wq0 = (tid & 31) * 4;
    const int wr1 = (tid + 256) >> 5, wq1 = (tid & 31) * 4;

    float4 rx0, rx1, rw0, rw1;

    // prologue: tile 0
    rx0 = *(const float4*)(Xb + (size_t)xr0 * HH + xq0);
    rx1 = *(const float4*)(Xb + (size_t)xr1 * HH + xq1);
    rw0 = *(const float4*)(W1 + (size_t)wr0 * AA + wq0);
    rw1 = *(const float4*)(W1 + (size_t)wr1 * AA + wq1);

    sX[xq0 + 0][xr0] = rx0.x; sX[xq0 + 1][xr0] = rx0.y;
    sX[xq0 + 2][xr0] = rx0.z; sX[xq0 + 3][xr0] = rx0.w;
    sX[xq1 + 0][xr1] = rx1.x; sX[xq1 + 1][xr1] = rx1.y;
    sX[xq1 + 2][xr1] = rx1.z; sX[xq1 + 3][xr1] = rx1.w;
    *(float4*)&sW[wr0][wq0] = rw0;
    *(float4*)&sW[wr1][wq1] = rw1;
    __syncthreads();

    for (int kt = 0; kt < 16; kt++) {
        if (kt < 15) {
            const int k0 = (kt + 1) * 16;
            rx0 = *(const float4*)(Xb + (size_t)xr0 * HH + k0 + xq0);
            rx1 = *(const float4*)(Xb + (size_t)xr1 * HH + k0 + xq1);
            rw0 = *(const float4*)(W1 + (size_t)(k0 + wr0) * AA + wq0);
            rw1 = *(const float4*)(W1 + (size_t)(k0 + wr1) * AA + wq1);
        }
#pragma unroll
        for (int k = 0; k < 16; k++) {
            // a: 4 packed row-pairs, straight 64-bit loads (adjacent rows)
            unsigned long long a2[4];
#pragma unroll
            for (int p = 0; p < 4; p++)
                a2[p] = *(const unsigned long long*)&sX[k][y * 8 + 2 * p];

            // b: 8 adjacent cols via 2x float4, duplicated into pairs
            const float4 bv0 = *(const float4*)&sW[k][x * 8];
            const float4 bv1 = *(const float4*)&sW[k][x * 8 + 4];
            unsigned long long b2r[8];
            b2r[0] = dup_f32(bv0.x); b2r[1] = dup_f32(bv0.y);
            b2r[2] = dup_f32(bv0.z); b2r[3] = dup_f32(bv0.w);
            b2r[4] = dup_f32(bv1.x); b2r[5] = dup_f32(bv1.y);
            b2r[6] = dup_f32(bv1.z); b2r[7] = dup_f32(bv1.w);

#pragma unroll
            for (int p = 0; p < 4; p++)
#pragma unroll
                for (int j = 0; j < 8; j++)
                    acc2[p][j] = fma_f32x2(a2[p], b2r[j], acc2[p][j]);
        }
        __syncthreads();
        if (kt < 15) {
            sX[xq0 + 0][xr0] = rx0.x; sX[xq0 + 1][xr0] = rx0.y;
            sX[xq0 + 2][xr0] = rx0.z; sX[xq0 + 3][xr0] = rx0.w;
            sX[xq1 + 0][xr1] = rx1.x; sX[xq1 + 1][xr1] = rx1.y;
            sX[xq1 + 2][xr1] = rx1.z; sX[xq1 + 3][xr1] = rx1.w;
            *(float4*)&sW[wr0][wq0] = rw0;
            *(float4*)&sW[wr1][wq1] = rw1;
            __syncthreads();
        }
    }

    // ---- epilogue: tanh, *W2, reduce over A ----
    float bb1[8], w2v[8];
#pragma unroll
    for (int j = 0; j < 8; j++) {
        const int col = x * 8 + j;
        bb1[j] = b1[col];
        w2v[j] = W2[col];
    }
    const float b2v = b2[0];

#pragma unroll
    for (int p = 0; p < 4; p++) {
        float s_lo = 0.0f, s_hi = 0.0f;
#pragma unroll
        for (int j = 0; j < 8; j++) {
            float lo, hi;
            unpack_f32x2(acc2[p][j], lo, hi);
            s_lo += tanhf(lo + bb1[j]) * w2v[j];
            s_hi += tanhf(hi + bb1[j]) * w2v[j];
        }
        // reduce across the 16 x-lanes
        s_lo += __shfl_xor_sync(0xffffffffu, s_lo, 8);
        s_lo += __shfl_xor_sync(0xffffffffu, s_lo, 4);
        s_lo += __shfl_xor_sync(0xffffffffu, s_lo, 2);
        s_lo += __shfl_xor_sync(0xffffffffu, s_lo, 1);
        s_hi += __shfl_xor_sync(0xffffffffu, s_hi, 8);
        s_hi += __shfl_xor_sync(0xffffffffu, s_hi, 4);
        s_hi += __shfl_xor_sync(0xffffffffu, s_hi, 2);
        s_hi += __shfl_xor_sync(0xffffffffu, s_hi, 1);
        if (x == 0) {
            g_scores[tok0 + y * 8 + 2 * p]     = s_lo + b2v;
            g_scores[tok0 + y * 8 + 2 * p + 1] = s_hi + b2v;
        }
    }
}

// ============================================================================
// Kernel 2: exact entmax-1.5 per batch row (S=4096). One block per row.
// ============================================================================
__global__ __launch_bounds__(512) void entmax_kernel(float* __restrict__ weights)
{
    const int b = blockIdx.x;
    const int tid = threadIdx.x;

    __shared__ float srt[SS];     // holds -(z) for ascending sort  (16KB)
    __shared__ float tau[SS];     // tau per k                       (16KB)
    __shared__ float aux1[512], aux2[512];
    __shared__ float red[512];
    __shared__ float s_bcast[2];

    const float* sc = g_scores + (size_t)b * SS;

    // z = score/2 ; find max
    float m = -1e30f;
    for (int i = tid; i < SS; i += 512) {
        float v = 0.5f * sc[i];
        srt[i] = v;
        m = fmaxf(m, v);
    }
    red[tid] = m;
    __syncthreads();
    for (int s = 256; s > 0; s >>= 1) {
        if (tid < s) red[tid] = fmaxf(red[tid], red[tid + s]);
        __syncthreads();
    }
    const float mx = red[0];
    __syncthreads();

    for (int i = tid; i < SS; i += 512)
        srt[i] = mx - srt[i];
    __syncthreads();

    // bitonic ascending sort
    for (int kk = 2; kk <= SS; kk <<= 1) {
        for (int jj = kk >> 1; jj > 0; jj >>= 1) {
            for (int i = tid; i < SS; i += 512) {
                const int l = i ^ jj;
                if (l > i) {
                    const float a = srt[i];
                    const float c = srt[l];
                    const bool up = ((i & kk) == 0);
                    if (up ? (a > c) : (a < c)) { srt[i] = c; srt[l] = a; }
                }
            }
            __syncthreads();
        }
    }

    // cumulative sums of zs and zs^2 (zs = -srt), 8 consecutive elems/thread
    const int base = tid * 8;
    float l1[8], l2[8];
    {
        float s1 = 0.0f, s2 = 0.0f;
#pragma unroll
        for (int j = 0; j < 8; j++) {
            const float v = -srt[base + j];
            s1 += v; s2 += v * v;
            l1[j] = s1; l2[j] = s2;
        }
        aux1[tid] = s1; aux2[tid] = s2;
    }
    __syncthreads();
    for (int off = 1; off < 512; off <<= 1) {
        float a1 = 0.0f, a2 = 0.0f;
        if (tid >= off) { a1 = aux1[tid - off]; a2 = aux2[tid - off]; }
        __syncthreads();
        aux1[tid] += a1; aux2[tid] += a2;
        __syncthreads();
    }
    const float off1 = aux1[tid] - l1[7];
    const float off2 = aux2[tid] - l2[7];

    float cnt = 0.0f;
#pragma unroll
    for (int j = 0; j < 8; j++) {
        const int k = base + j;
        const float fk = (float)(k + 1);
        const float c1 = off1 + l1[j];
        const float c2 = off2 + l2[j];
        const float mean = c1 / fk;
        const float msq  = c2 / fk;
        const float ssv  = fk * (msq - mean * mean);
        const float delta = fmaxf((1.0f - ssv) / fk, 0.0f);
        const float t = mean - sqrtf(delta);
        tau[k] = t;
        const float zsk = -srt[k];
        if (t <= zsk) cnt += 1.0f;
    }
    red[tid] = cnt;
    __syncthreads();
    for (int s = 256; s > 0; s >>= 1) {
        if (tid < s) red[tid] += red[tid + s];
        __syncthreads();
    }
    if (tid == 0) {
        const int k_star = (int)(red[0] + 0.5f);
        s_bcast[1] = tau[k_star - 1];
    }
    __syncthreads();
    const float tau_star = s_bcast[1];

    float* wout = weights + (size_t)b * SS;
    for (int i = tid; i < SS; i += 512) {
        const float v = 0.5f * sc[i] - mx - tau_star;
        const float r = v > 0.0f ? v : 0.0f;
        wout[i] = r * r;
    }
}

// ============================================================================
// Kernel 3: context partials.  grid (B, 32), 256 threads (one per h).
// ============================================================================
__global__ __launch_bounds__(256) void ctx_partial_kernel(
    const float* __restrict__ X, const float* __restrict__ weights)
{
    const int b = blockIdx.x;
    const int c = blockIdx.y;
    const int h = threadIdx.x;

    __shared__ float ws[128];
    if (h < 128) ws[h] = weights[(size_t)b * SS + c * 128 + h];
    __syncthreads();

    const float* xb = X + ((size_t)b * SS + (size_t)c * 128) * HH;
    float acc = 0.0f;
#pragma unroll 2
    for (int s = 0; s < 128; s++) {
        const float w = ws[s];
        if (w != 0.0f)
            acc = fmaf(xb[(size_t)s * HH + h], w, acc);
    }
    g_partial[((size_t)b * 32 + c) * HH + h] = acc;
}

// Kernel 4: final reduce of 32 partials -> context [B, H]
__global__ __launch_bounds__(256) void ctx_reduce_kernel(float* __restrict__ ctx)
{
    const int b = blockIdx.x;
    const int h = threadIdx.x;
    float s = 0.0f;
#pragma unroll
    for (int c = 0; c < 32; c++)
        s += g_partial[((size_t)b * 32 + c) * HH + h];
    ctx[(size_t)b * HH + h] = s;
}

// ============================================================================
extern "C" void kernel_launch(void* const* d_in, const int* in_sizes, int n_in,
                              void* d_out, int out_size)
{
    const float* X  = (const float*)d_in[0];   // [64,4096,256]
    const float* W1 = (const float*)d_in[1];   // [256,128]
    const float* b1 = (const float*)d_in[2];   // [128]
    const float* W2 = (const float*)d_in[3];   // [128,1]
    const float* b2 = (const float*)d_in[4];   // [1]

    float* out = (float*)d_out;
    float* ctx = out;                 // [64,256]  (tuple elem 0)
    float* wts = out + BB * HH;       // [64,4096] (tuple elem 1)

    scores_kernel<<<NTOK / 128, 256>>>(X, W1, b1, W2, b2);
    entmax_kernel<<<BB, 512>>>(wts);
    ctx_partial_kernel<<<dim3(BB, 32), 256>>>(X, wts);
    ctx_reduce_kernel<<<BB, 256>>>(ctx);
}

// round 4
// speedup vs baseline: 1.6928x; 1.5915x over previous
#include <cuda_runtime.h>
#include <cuda_bf16.h>
#include <cstdint>

// Problem constants
#define BB 64
#define SS 4096
#define HH 256
#define AA 128
#define NTOK (BB * SS)          // 262144 tokens

#define PADK 72                 // bf16 elems per smem row (144B, conflict-free)

// ---------------- scratch (device globals; no allocation allowed) ----------
__device__ float g_scores[NTOK];                    // [B,S] pre-entmax scores
__device__ float g_partial[BB * 32 * HH];           // context partials
// W1 pre-converted to bf16 hi/lo, padded chunk layout: [4 chunks][128 n][72]
__device__ __nv_bfloat16 g_Bhi[4 * 128 * PADK];
__device__ __nv_bfloat16 g_Blo[4 * 128 * PADK];

// ---------------- PTX helpers ----------------------------------------------
__device__ __forceinline__ uint32_t s2u(const void* p) {
    uint32_t a;
    asm("{ .reg .u64 t; cvta.to.shared.u64 t, %1; cvt.u32.u64 %0, t; }"
        : "=r"(a) : "l"(p));
    return a;
}

#define LDSM_X4(r0, r1, r2, r3, addr)                                        \
    asm volatile("ldmatrix.sync.aligned.m8n8.x4.shared.b16 {%0,%1,%2,%3}, [%4];" \
                 : "=r"(r0), "=r"(r1), "=r"(r2), "=r"(r3) : "r"(addr))

#define MMA_BF16(d0, d1, d2, d3, a0, a1, a2, a3, b0, b1)                     \
    asm volatile("mma.sync.aligned.m16n8k16.row.col.f32.bf16.bf16.f32 "      \
                 "{%0,%1,%2,%3}, {%4,%5,%6,%7}, {%8,%9}, {%0,%1,%2,%3};"     \
                 : "+f"(d0), "+f"(d1), "+f"(d2), "+f"(d3)                    \
                 : "r"(a0), "r"(a1), "r"(a2), "r"(a3), "r"(b0), "r"(b1))

// ============================================================================
// Kernel 0: convert W1 [256,128] fp32 -> bf16 hi/lo, padded chunk layout.
// ============================================================================
__global__ __launch_bounds__(256) void convW_kernel(const float* __restrict__ W1)
{
    const int idx = blockIdx.x * 256 + threadIdx.x;   // 0..32767
    const int k = idx >> 7;       // H index 0..255
    const int n = idx & 127;      // A index 0..127
    const float w = W1[idx];
    const __nv_bfloat16 hi = __float2bfloat16(w);
    const float hf = __bfloat162float(hi);
    const __nv_bfloat16 lo = __float2bfloat16(w - hf);
    const int chunk = k >> 6;
    const int kc = k & 63;
    const int pos = (chunk * 128 + n) * PADK + kc;
    g_Bhi[pos] = hi;
    g_Blo[pos] = lo;
}

// ============================================================================
// Kernel 1: scores GEMM via mma.sync bf16 hi/lo split + fused tanh/W2
// epilogue. One CTA per 128 tokens; 8 warps, each m16 x n128.
// ============================================================================
// dynamic smem byte offsets
#define OFF_AHI   0
#define OFF_ALO   18432
#define OFF_BHI   36864
#define OFF_BLO   55296
#define OFF_B1S   73728
#define OFF_W2S   74240
#define SMEM_BYTES 74752

__global__ __launch_bounds__(256) void scores_mma_kernel(
    const float* __restrict__ X,    // [NTOK, 256]
    const float* __restrict__ b1,   // [128]
    const float* __restrict__ W2,   // [128]
    const float* __restrict__ b2)   // [1]
{
    extern __shared__ __align__(16) char smem[];
    const uint32_t sb = s2u(smem);
    const int tid = threadIdx.x;
    const int wid = tid >> 5;
    const int lane = tid & 31;
    const int tok0 = blockIdx.x * 128;

    if (tid < 128) {
        *(float*)(smem + OFF_B1S + tid * 4) = b1[tid];
        *(float*)(smem + OFF_W2S + tid * 4) = W2[tid];
    }

    float acc[16][4];
#pragma unroll
    for (int nf = 0; nf < 16; nf++)
#pragma unroll
        for (int i = 0; i < 4; i++) acc[nf][i] = 0.0f;

    const int row  = tid >> 1;      // 0..127 (token row in tile)
    const int half = tid & 1;       // 32-col half of the 64-col chunk
    const float4* Xr = (const float4*)(X + (size_t)(tok0 + row) * HH);

    // ldmatrix lane addressing
    const int grp = lane >> 3;            // 0..3
    const uint32_t a_row = (uint32_t)(wid * 16 + (lane & 7) + (grp & 1) * 8);
    const uint32_t a_kad = (uint32_t)((grp >> 1) * 8) * 2;
    const uint32_t b_rowbase = (uint32_t)((lane & 7) + (grp >> 1) * 8);
    const uint32_t b_kad = (uint32_t)((grp & 1) * 8) * 2;

    for (int c = 0; c < 4; c++) {
        // ---- copy B chunk (padded layout, linear 18432B each) ----
        {
            const uint4* srch = (const uint4*)g_Bhi + c * 1152;
            const uint4* srcl = (const uint4*)g_Blo + c * 1152;
            uint4* dsth = (uint4*)(smem + OFF_BHI);
            uint4* dstl = (uint4*)(smem + OFF_BLO);
#pragma unroll
            for (int i = 0; i < 5; i++) {
                const int idx = tid + i * 256;
                if (idx < 1152) {
                    dsth[idx] = srch[idx];
                    dstl[idx] = srcl[idx];
                }
            }
        }
        // ---- load + convert A chunk: 128 rows x 64 k (fp32 -> bf16 hi/lo) -
        {
#pragma unroll
            for (int q = 0; q < 8; q++) {
                const float4 v = Xr[c * 16 + half * 8 + q];
                __nv_bfloat162 h0 = __floats2bfloat162_rn(v.x, v.y);
                __nv_bfloat162 h1 = __floats2bfloat162_rn(v.z, v.w);
                float rx = v.x - __bfloat162float(__low2bfloat16(h0));
                float ry = v.y - __bfloat162float(__high2bfloat16(h0));
                float rz = v.z - __bfloat162float(__low2bfloat16(h1));
                float rw = v.w - __bfloat162float(__high2bfloat16(h1));
                __nv_bfloat162 l0 = __floats2bfloat162_rn(rx, ry);
                __nv_bfloat162 l1 = __floats2bfloat162_rn(rz, rw);

                const uint32_t boff = (uint32_t)row * (PADK * 2) +
                                      (uint32_t)(half * 64 + q * 8);
                uint2 hw, lw;
                hw.x = *(uint32_t*)&h0; hw.y = *(uint32_t*)&h1;
                lw.x = *(uint32_t*)&l0; lw.y = *(uint32_t*)&l1;
                *(uint2*)(smem + OFF_AHI + boff) = hw;
                *(uint2*)(smem + OFF_ALO + boff) = lw;
            }
        }
        __syncthreads();

        // ---- 4 k-steps of 16, 48 HMMA each ----
#pragma unroll
        for (int ks = 0; ks < 4; ks++) {
            const uint32_t k0b = (uint32_t)(ks * 16) * 2;
            const uint32_t a_off = a_row * (PADK * 2) + k0b + a_kad;
            uint32_t ah0, ah1, ah2, ah3, al0, al1, al2, al3;
            LDSM_X4(ah0, ah1, ah2, ah3, sb + OFF_AHI + a_off);
            LDSM_X4(al0, al1, al2, al3, sb + OFF_ALO + a_off);
#pragma unroll
            for (int nf2 = 0; nf2 < 8; nf2++) {
                const uint32_t b_off =
                    (b_rowbase + (uint32_t)(nf2 * 16)) * (PADK * 2) + k0b + b_kad;
                uint32_t bh0, bh1, bh2, bh3, bl0, bl1, bl2, bl3;
                LDSM_X4(bh0, bh1, bh2, bh3, sb + OFF_BHI + b_off);
                LDSM_X4(bl0, bl1, bl2, bl3, sb + OFF_BLO + b_off);
                float* d0 = acc[nf2 * 2];
                float* d1 = acc[nf2 * 2 + 1];
                MMA_BF16(d0[0], d0[1], d0[2], d0[3], ah0, ah1, ah2, ah3, bh0, bh1);
                MMA_BF16(d0[0], d0[1], d0[2], d0[3], ah0, ah1, ah2, ah3, bl0, bl1);
                MMA_BF16(d0[0], d0[1], d0[2], d0[3], al0, al1, al2, al3, bh0, bh1);
                MMA_BF16(d1[0], d1[1], d1[2], d1[3], ah0, ah1, ah2, ah3, bh2, bh3);
                MMA_BF16(d1[0], d1[1], d1[2], d1[3], ah0, ah1, ah2, ah3, bl2, bl3);
                MMA_BF16(d1[0], d1[1], d1[2], d1[3], al0, al1, al2, al3, bh2, bh3);
            }
        }
        __syncthreads();
    }

    // ---- epilogue: tanh dot W2, quad reduce ----
    const float b2v = b2[0];
    float s0 = 0.0f, s1 = 0.0f;
#pragma unroll
    for (int nf = 0; nf < 16; nf++) {
        const int c0 = nf * 8 + (lane & 3) * 2;
        const float bb0 = *(const float*)(smem + OFF_B1S + c0 * 4);
        const float bb1v = *(const float*)(smem + OFF_B1S + (c0 + 1) * 4);
        const float ww0 = *(const float*)(smem + OFF_W2S + c0 * 4);
        const float ww1 = *(const float*)(smem + OFF_W2S + (c0 + 1) * 4);
        s0 += tanhf(acc[nf][0] + bb0) * ww0 + tanhf(acc[nf][1] + bb1v) * ww1;
        s1 += tanhf(acc[nf][2] + bb0) * ww0 + tanhf(acc[nf][3] + bb1v) * ww1;
    }
    s0 += __shfl_xor_sync(0xffffffffu, s0, 1);
    s0 += __shfl_xor_sync(0xffffffffu, s0, 2);
    s1 += __shfl_xor_sync(0xffffffffu, s1, 1);
    s1 += __shfl_xor_sync(0xffffffffu, s1, 2);
    if ((lane & 3) == 0) {
        const int r = wid * 16 + (lane >> 2);
        g_scores[tok0 + r]     = s0 + b2v;
        g_scores[tok0 + r + 8] = s1 + b2v;
    }
}

// ============================================================================
// Kernel 2: exact entmax-1.5 per batch row (S=4096). One block per row.
// ============================================================================
__global__ __launch_bounds__(512) void entmax_kernel(float* __restrict__ weights)
{
    const int b = blockIdx.x;
    const int tid = threadIdx.x;

    __shared__ float srt[SS];
    __shared__ float tau[SS];
    __shared__ float aux1[512], aux2[512];
    __shared__ float red[512];
    __shared__ float s_bcast[2];

    const float* sc = g_scores + (size_t)b * SS;

    float m = -1e30f;
    for (int i = tid; i < SS; i += 512) {
        float v = 0.5f * sc[i];
        srt[i] = v;
        m = fmaxf(m, v);
    }
    red[tid] = m;
    __syncthreads();
    for (int s = 256; s > 0; s >>= 1) {
        if (tid < s) red[tid] = fmaxf(red[tid], red[tid + s]);
        __syncthreads();
    }
    const float mx = red[0];
    __syncthreads();

    for (int i = tid; i < SS; i += 512)
        srt[i] = mx - srt[i];
    __syncthreads();

    for (int kk = 2; kk <= SS; kk <<= 1) {
        for (int jj = kk >> 1; jj > 0; jj >>= 1) {
            for (int i = tid; i < SS; i += 512) {
                const int l = i ^ jj;
                if (l > i) {
                    const float a = srt[i];
                    const float c = srt[l];
                    const bool up = ((i & kk) == 0);
                    if (up ? (a > c) : (a < c)) { srt[i] = c; srt[l] = a; }
                }
            }
            __syncthreads();
        }
    }

    const int base = tid * 8;
    float l1[8], l2[8];
    {
        float s1 = 0.0f, s2 = 0.0f;
#pragma unroll
        for (int j = 0; j < 8; j++) {
            const float v = -srt[base + j];
            s1 += v; s2 += v * v;
            l1[j] = s1; l2[j] = s2;
        }
        aux1[tid] = s1; aux2[tid] = s2;
    }
    __syncthreads();
    for (int off = 1; off < 512; off <<= 1) {
        float a1 = 0.0f, a2 = 0.0f;
        if (tid >= off) { a1 = aux1[tid - off]; a2 = aux2[tid - off]; }
        __syncthreads();
        aux1[tid] += a1; aux2[tid] += a2;
        __syncthreads();
    }
    const float off1 = aux1[tid] - l1[7];
    const float off2 = aux2[tid] - l2[7];

    float cnt = 0.0f;
#pragma unroll
    for (int j = 0; j < 8; j++) {
        const int k = base + j;
        const float fk = (float)(k + 1);
        const float c1 = off1 + l1[j];
        const float c2 = off2 + l2[j];
        const float mean = c1 / fk;
        const float msq  = c2 / fk;
        const float ssv  = fk * (msq - mean * mean);
        const float delta = fmaxf((1.0f - ssv) / fk, 0.0f);
        const float t = mean - sqrtf(delta);
        tau[k] = t;
        const float zsk = -srt[k];
        if (t <= zsk) cnt += 1.0f;
    }
    red[tid] = cnt;
    __syncthreads();
    for (int s = 256; s > 0; s >>= 1) {
        if (tid < s) red[tid] += red[tid + s];
        __syncthreads();
    }
    if (tid == 0) {
        const int k_star = (int)(red[0] + 0.5f);
        s_bcast[1] = tau[k_star - 1];
    }
    __syncthreads();
    const float tau_star = s_bcast[1];

    float* wout = weights + (size_t)b * SS;
    for (int i = tid; i < SS; i += 512) {
        const float v = 0.5f * sc[i] - mx - tau_star;
        const float r = v > 0.0f ? v : 0.0f;
        wout[i] = r * r;
    }
}

// ============================================================================
// Kernel 3: context partials.  grid (B, 32), 256 threads (one per h).
// ============================================================================
__global__ __launch_bounds__(256) void ctx_partial_kernel(
    const float* __restrict__ X, const float* __restrict__ weights)
{
    const int b = blockIdx.x;
    const int c = blockIdx.y;
    const int h = threadIdx.x;

    __shared__ float ws[128];
    if (h < 128) ws[h] = weights[(size_t)b * SS + c * 128 + h];
    __syncthreads();

    const float* xb = X + ((size_t)b * SS + (size_t)c * 128) * HH;
    float acc = 0.0f;
#pragma unroll 2
    for (int s = 0; s < 128; s++) {
        const float w = ws[s];
        if (w != 0.0f)
            acc = fmaf(xb[(size_t)s * HH + h], w, acc);
    }
    g_partial[((size_t)b * 32 + c) * HH + h] = acc;
}

// Kernel 4: final reduce of 32 partials -> context [B, H]
__global__ __launch_bounds__(256) void ctx_reduce_kernel(float* __restrict__ ctx)
{
    const int b = blockIdx.x;
    const int h = threadIdx.x;
    float s = 0.0f;
#pragma unroll
    for (int c = 0; c < 32; c++)
        s += g_partial[((size_t)b * 32 + c) * HH + h];
    ctx[(size_t)b * HH + h] = s;
}

// ============================================================================
extern "C" void kernel_launch(void* const* d_in, const int* in_sizes, int n_in,
                              void* d_out, int out_size)
{
    const float* X  = (const float*)d_in[0];   // [64,4096,256]
    const float* W1 = (const float*)d_in[1];   // [256,128]
    const float* b1 = (const float*)d_in[2];   // [128]
    const float* W2 = (const float*)d_in[3];   // [128,1]
    const float* b2 = (const float*)d_in[4];   // [1]

    float* out = (float*)d_out;
    float* ctx = out;                 // [64,256]  (tuple elem 0)
    float* wts = out + BB * HH;       // [64,4096] (tuple elem 1)

    cudaFuncSetAttribute(scores_mma_kernel,
                         cudaFuncAttributeMaxDynamicSharedMemorySize, SMEM_BYTES);

    convW_kernel<<<128, 256>>>(W1);
    scores_mma_kernel<<<NTOK / 128, 256, SMEM_BYTES>>>(X, b1, W2, b2);
    entmax_kernel<<<BB, 512>>>(wts);
    ctx_partial_kernel<<<dim3(BB, 32), 256>>>(X, wts);
    ctx_reduce_kernel<<<BB, 256>>>(ctx);
}

// round 5
// speedup vs baseline: 1.8029x; 1.0650x over previous
#include <cuda_runtime.h>
#include <cuda_bf16.h>
#include <cstdint>

// Problem constants
#define BB 64
#define SS 4096
#define HH 256
#define AA 128
#define NTOK (BB * SS)          // 262144 tokens

#define PADK 72                 // bf16 elems per smem row (144B, conflict-free)

// ---------------- scratch (device globals; no allocation allowed) ----------
__device__ float g_scores[NTOK];                    // [B,S] pre-entmax scores
__device__ float g_partial[BB * 8 * HH];            // context partials
__device__ int   g_nzidx[NTOK];                     // compacted support idx
__device__ float g_nzw[NTOK];                       // compacted support w
__device__ int   g_nzcnt[BB];                       // support count per batch
// W1 pre-converted to bf16 hi/lo, padded chunk layout: [4 chunks][128 n][72]
__device__ __nv_bfloat16 g_Bhi[4 * 128 * PADK];
__device__ __nv_bfloat16 g_Blo[4 * 128 * PADK];

// ---------------- PTX helpers ----------------------------------------------
__device__ __forceinline__ uint32_t s2u(const void* p) {
    uint32_t a;
    asm("{ .reg .u64 t; cvta.to.shared.u64 t, %1; cvt.u32.u64 %0, t; }"
        : "=r"(a) : "l"(p));
    return a;
}

#define LDSM_X4(r0, r1, r2, r3, addr)                                        \
    asm volatile("ldmatrix.sync.aligned.m8n8.x4.shared.b16 {%0,%1,%2,%3}, [%4];" \
                 : "=r"(r0), "=r"(r1), "=r"(r2), "=r"(r3) : "r"(addr))

#define MMA_BF16(d0, d1, d2, d3, a0, a1, a2, a3, b0, b1)                     \
    asm volatile("mma.sync.aligned.m16n8k16.row.col.f32.bf16.bf16.f32 "      \
                 "{%0,%1,%2,%3}, {%4,%5,%6,%7}, {%8,%9}, {%0,%1,%2,%3};"     \
                 : "+f"(d0), "+f"(d1), "+f"(d2), "+f"(d3)                    \
                 : "r"(a0), "r"(a1), "r"(a2), "r"(a3), "r"(b0), "r"(b1))

#define CP_ASYNC16(dst, src)                                                 \
    asm volatile("cp.async.cg.shared.global [%0], [%1], 16;"                 \
                 :: "r"(dst), "l"(src))
#define CP_COMMIT() asm volatile("cp.async.commit_group;" ::: "memory")
#define CP_WAIT0()  asm volatile("cp.async.wait_group 0;" ::: "memory")

// ============================================================================
// Kernel 0: convert W1 [256,128] fp32 -> bf16 hi/lo, padded chunk layout.
// ============================================================================
__global__ __launch_bounds__(256) void convW_kernel(const float* __restrict__ W1)
{
    const int idx = blockIdx.x * 256 + threadIdx.x;   // 0..32767
    const int k = idx >> 7;       // H index 0..255
    const int n = idx & 127;      // A index 0..127
    const float w = W1[idx];
    const __nv_bfloat16 hi = __float2bfloat16(w);
    const float hf = __bfloat162float(hi);
    const __nv_bfloat16 lo = __float2bfloat16(w - hf);
    const int chunk = k >> 6;
    const int kc = k & 63;
    const int pos = (chunk * 128 + n) * PADK + kc;
    g_Bhi[pos] = hi;
    g_Blo[pos] = lo;
}

// ============================================================================
// Kernel 1: scores GEMM via mma.sync bf16 hi/lo split + fused tanh/W2
// epilogue. One CTA per 128 tokens; 8 warps, each m16 x n128.
// Pipelined: cp.async for B tiles, register-staged prefetch for A.
// ============================================================================
// dynamic smem byte offsets
#define OFF_AHI   0
#define OFF_ALO   18432
#define OFF_BHI   36864
#define OFF_BLO   55296
#define OFF_B1S   73728
#define OFF_W2S   74240
#define SMEM_BYTES 74752

__global__ __launch_bounds__(256, 2) void scores_mma_kernel(
    const float* __restrict__ X,    // [NTOK, 256]
    const float* __restrict__ b1,   // [128]
    const float* __restrict__ W2,   // [128]
    const float* __restrict__ b2)   // [1]
{
    extern __shared__ __align__(16) char smem[];
    const uint32_t sb = s2u(smem);
    const int tid = threadIdx.x;
    const int wid = tid >> 5;
    const int lane = tid & 31;
    const int tok0 = blockIdx.x * 128;

    if (tid < 128) {
        *(float*)(smem + OFF_B1S + tid * 4) = b1[tid];
        *(float*)(smem + OFF_W2S + tid * 4) = W2[tid];
    }

    float acc[16][4];
#pragma unroll
    for (int nf = 0; nf < 16; nf++)
#pragma unroll
        for (int i = 0; i < 4; i++) acc[nf][i] = 0.0f;

    const int row  = tid >> 1;      // 0..127 (token row in tile)
    const int half = tid & 1;       // 32-col half of the 64-col chunk
    const float4* Xr = (const float4*)(X + (size_t)(tok0 + row) * HH);
    const uint32_t a_boff = (uint32_t)row * (PADK * 2) + (uint32_t)(half * 64);

    // ldmatrix lane addressing
    const int grp = lane >> 3;            // 0..3
    const uint32_t a_row = (uint32_t)(wid * 16 + (lane & 7) + (grp & 1) * 8);
    const uint32_t a_kad = (uint32_t)((grp >> 1) * 8) * 2;
    const uint32_t b_rowbase = (uint32_t)((lane & 7) + (grp >> 1) * 8);
    const uint32_t b_kad = (uint32_t)((grp & 1) * 8) * 2;

    // register-staged A prefetch (chunk 0)
    float4 v[8];
#pragma unroll
    for (int q = 0; q < 8; q++) v[q] = Xr[half * 8 + q];

    for (int c = 0; c < 4; c++) {
        // ---- B chunk via cp.async (L2-resident, 18432B each) ----
        {
            const char* srch = (const char*)(g_Bhi + c * 128 * PADK);
            const char* srcl = (const char*)(g_Blo + c * 128 * PADK);
#pragma unroll
            for (int i = 0; i < 5; i++) {
                const int idx = tid + i * 256;
                if (idx < 1152) {
                    CP_ASYNC16(sb + OFF_BHI + idx * 16, srch + idx * 16);
                    CP_ASYNC16(sb + OFF_BLO + idx * 16, srcl + idx * 16);
                }
            }
            CP_COMMIT();
        }
        // ---- convert staged A chunk -> smem hi/lo ----
        {
#pragma unroll
            for (int q = 0; q < 8; q++) {
                const float4 vv = v[q];
                __nv_bfloat162 h0 = __floats2bfloat162_rn(vv.x, vv.y);
                __nv_bfloat162 h1 = __floats2bfloat162_rn(vv.z, vv.w);
                float rx = vv.x - __bfloat162float(__low2bfloat16(h0));
                float ry = vv.y - __bfloat162float(__high2bfloat16(h0));
                float rz = vv.z - __bfloat162float(__low2bfloat16(h1));
                float rw = vv.w - __bfloat162float(__high2bfloat16(h1));
                __nv_bfloat162 l0 = __floats2bfloat162_rn(rx, ry);
                __nv_bfloat162 l1 = __floats2bfloat162_rn(rz, rw);

                const uint32_t boff = a_boff + (uint32_t)(q * 8);
                uint2 hw, lw;
                hw.x = *(uint32_t*)&h0; hw.y = *(uint32_t*)&h1;
                lw.x = *(uint32_t*)&l0; lw.y = *(uint32_t*)&l1;
                *(uint2*)(smem + OFF_AHI + boff) = hw;
                *(uint2*)(smem + OFF_ALO + boff) = lw;
            }
        }
        // ---- prefetch next A chunk into regs (latency hidden by MMAs) ----
        if (c < 3) {
#pragma unroll
            for (int q = 0; q < 8; q++) v[q] = Xr[(c + 1) * 16 + half * 8 + q];
        }
        CP_WAIT0();
        __syncthreads();

        // ---- 4 k-steps of 16, 48 HMMA each ----
#pragma unroll
        for (int ks = 0; ks < 4; ks++) {
            const uint32_t k0b = (uint32_t)(ks * 16) * 2;
            const uint32_t a_off = a_row * (PADK * 2) + k0b + a_kad;
            uint32_t ah0, ah1, ah2, ah3, al0, al1, al2, al3;
            LDSM_X4(ah0, ah1, ah2, ah3, sb + OFF_AHI + a_off);
            LDSM_X4(al0, al1, al2, al3, sb + OFF_ALO + a_off);
#pragma unroll
            for (int nf2 = 0; nf2 < 8; nf2++) {
                const uint32_t b_off =
                    (b_rowbase + (uint32_t)(nf2 * 16)) * (PADK * 2) + k0b + b_kad;
                uint32_t bh0, bh1, bh2, bh3, bl0, bl1, bl2, bl3;
                LDSM_X4(bh0, bh1, bh2, bh3, sb + OFF_BHI + b_off);
                LDSM_X4(bl0, bl1, bl2, bl3, sb + OFF_BLO + b_off);
                float* d0 = acc[nf2 * 2];
                float* d1 = acc[nf2 * 2 + 1];
                MMA_BF16(d0[0], d0[1], d0[2], d0[3], ah0, ah1, ah2, ah3, bh0, bh1);
                MMA_BF16(d0[0], d0[1], d0[2], d0[3], ah0, ah1, ah2, ah3, bl0, bl1);
                MMA_BF16(d0[0], d0[1], d0[2], d0[3], al0, al1, al2, al3, bh0, bh1);
                MMA_BF16(d1[0], d1[1], d1[2], d1[3], ah0, ah1, ah2, ah3, bh2, bh3);
                MMA_BF16(d1[0], d1[1], d1[2], d1[3], ah0, ah1, ah2, ah3, bl2, bl3);
                MMA_BF16(d1[0], d1[1], d1[2], d1[3], al0, al1, al2, al3, bh2, bh3);
            }
        }
        __syncthreads();
    }

    // ---- epilogue: tanh dot W2, quad reduce ----
    const float b2v = b2[0];
    float s0 = 0.0f, s1 = 0.0f;
#pragma unroll
    for (int nf = 0; nf < 16; nf++) {
        const int c0 = nf * 8 + (lane & 3) * 2;
        const float bb0 = *(const float*)(smem + OFF_B1S + c0 * 4);
        const float bb1v = *(const float*)(smem + OFF_B1S + (c0 + 1) * 4);
        const float ww0 = *(const float*)(smem + OFF_W2S + c0 * 4);
        const float ww1 = *(const float*)(smem + OFF_W2S + (c0 + 1) * 4);
        s0 += tanhf(acc[nf][0] + bb0) * ww0 + tanhf(acc[nf][1] + bb1v) * ww1;
        s1 += tanhf(acc[nf][2] + bb0) * ww0 + tanhf(acc[nf][3] + bb1v) * ww1;
    }
    s0 += __shfl_xor_sync(0xffffffffu, s0, 1);
    s0 += __shfl_xor_sync(0xffffffffu, s0, 2);
    s1 += __shfl_xor_sync(0xffffffffu, s1, 1);
    s1 += __shfl_xor_sync(0xffffffffu, s1, 2);
    if ((lane & 3) == 0) {
        const int r = wid * 16 + (lane >> 2);
        g_scores[tok0 + r]     = s0 + b2v;
        g_scores[tok0 + r + 8] = s1 + b2v;
    }
}

// ============================================================================
// Kernel 2: exact entmax-1.5 per batch row (S=4096) + deterministic
// compaction of the support set (index order preserved).
// ============================================================================
__global__ __launch_bounds__(512) void entmax_kernel(float* __restrict__ weights)
{
    const int b = blockIdx.x;
    const int tid = threadIdx.x;

    __shared__ float srt[SS];
    __shared__ float tau[SS];
    __shared__ float aux1[512], aux2[512];
    __shared__ float red[512];
    __shared__ int   iscan[512];
    __shared__ float s_bcast[2];

    const float* sc = g_scores + (size_t)b * SS;

    float m = -1e30f;
    for (int i = tid; i < SS; i += 512) {
        float v = 0.5f * sc[i];
        srt[i] = v;
        m = fmaxf(m, v);
    }
    red[tid] = m;
    __syncthreads();
    for (int s = 256; s > 0; s >>= 1) {
        if (tid < s) red[tid] = fmaxf(red[tid], red[tid + s]);
        __syncthreads();
    }
    const float mx = red[0];
    __syncthreads();

    for (int i = tid; i < SS; i += 512)
        srt[i] = mx - srt[i];
    __syncthreads();

    for (int kk = 2; kk <= SS; kk <<= 1) {
        for (int jj = kk >> 1; jj > 0; jj >>= 1) {
            for (int i = tid; i < SS; i += 512) {
                const int l = i ^ jj;
                if (l > i) {
                    const float a = srt[i];
                    const float c = srt[l];
                    const bool up = ((i & kk) == 0);
                    if (up ? (a > c) : (a < c)) { srt[i] = c; srt[l] = a; }
                }
            }
            __syncthreads();
        }
    }

    const int base = tid * 8;
    float l1[8], l2[8];
    {
        float s1 = 0.0f, s2 = 0.0f;
#pragma unroll
        for (int j = 0; j < 8; j++) {
            const float v = -srt[base + j];
            s1 += v; s2 += v * v;
            l1[j] = s1; l2[j] = s2;
        }
        aux1[tid] = s1; aux2[tid] = s2;
    }
    __syncthreads();
    for (int off = 1; off < 512; off <<= 1) {
        float a1 = 0.0f, a2 = 0.0f;
        if (tid >= off) { a1 = aux1[tid - off]; a2 = aux2[tid - off]; }
        __syncthreads();
        aux1[tid] += a1; aux2[tid] += a2;
        __syncthreads();
    }
    const float off1 = aux1[tid] - l1[7];
    const float off2 = aux2[tid] - l2[7];

    float cnt = 0.0f;
#pragma unroll
    for (int j = 0; j < 8; j++) {
        const int k = base + j;
        const float fk = (float)(k + 1);
        const float c1 = off1 + l1[j];
        const float c2 = off2 + l2[j];
        const float mean = c1 / fk;
        const float msq  = c2 / fk;
        const float ssv  = fk * (msq - mean * mean);
        const float delta = fmaxf((1.0f - ssv) / fk, 0.0f);
        const float t = mean - sqrtf(delta);
        tau[k] = t;
        const float zsk = -srt[k];
        if (t <= zsk) cnt += 1.0f;
    }
    red[tid] = cnt;
    __syncthreads();
    for (int s = 256; s > 0; s >>= 1) {
        if (tid < s) red[tid] += red[tid + s];
        __syncthreads();
    }
    if (tid == 0) {
        const int k_star = (int)(red[0] + 0.5f);
        s_bcast[1] = tau[k_star - 1];
    }
    __syncthreads();
    const float tau_star = s_bcast[1];

    // dense weights (contiguous 8 per thread) + support compaction
    float* wout = weights + (size_t)b * SS;
    float wv[8];
    int mycnt = 0;
#pragma unroll
    for (int j = 0; j < 8; j++) {
        const int i = base + j;
        const float v = 0.5f * sc[i] - mx - tau_star;
        const float r = v > 0.0f ? v : 0.0f;
        const float w = r * r;
        wv[j] = w;
        wout[i] = w;
        if (w > 0.0f) mycnt++;
    }
    iscan[tid] = mycnt;
    __syncthreads();
    for (int off = 1; off < 512; off <<= 1) {
        int a = 0;
        if (tid >= off) a = iscan[tid - off];
        __syncthreads();
        iscan[tid] += a;
        __syncthreads();
    }
    int pos = iscan[tid] - mycnt;   // exclusive prefix
#pragma unroll
    for (int j = 0; j < 8; j++) {
        if (wv[j] > 0.0f) {
            g_nzidx[(size_t)b * SS + pos] = base + j;
            g_nzw[(size_t)b * SS + pos]   = wv[j];
            pos++;
        }
    }
    if (tid == 511) g_nzcnt[b] = iscan[511];
}

// ============================================================================
// Kernel 3: sparse context partials.  grid (B, 8), 256 threads (one per h).
// ============================================================================
__global__ __launch_bounds__(256) void ctx_sparse_kernel(const float* __restrict__ X)
{
    const int b = blockIdx.x;
    const int sl = blockIdx.y;
    const int h = threadIdx.x;

    __shared__ int   sidx[512];
    __shared__ float swt[512];

    const int cnt = g_nzcnt[b];
    const int per = (cnt + 7) >> 3;
    const int s0 = sl * per;
    int s1 = s0 + per; if (s1 > cnt) s1 = cnt;
    const int n = s1 - s0;

    for (int t = h; t < n; t += 256) {
        sidx[t] = g_nzidx[(size_t)b * SS + s0 + t];
        swt[t]  = g_nzw[(size_t)b * SS + s0 + t];
    }
    __syncthreads();

    const float* Xb = X + (size_t)b * SS * HH;
    float acc = 0.0f;
    int i = 0;
    for (; i + 4 <= n; i += 4) {
        const float x0 = Xb[(size_t)sidx[i]     * HH + h];
        const float x1 = Xb[(size_t)sidx[i + 1] * HH + h];
        const float x2 = Xb[(size_t)sidx[i + 2] * HH + h];
        const float x3 = Xb[(size_t)sidx[i + 3] * HH + h];
        acc = fmaf(x0, swt[i], acc);
        acc = fmaf(x1, swt[i + 1], acc);
        acc = fmaf(x2, swt[i + 2], acc);
        acc = fmaf(x3, swt[i + 3], acc);
    }
    for (; i < n; i++)
        acc = fmaf(Xb[(size_t)sidx[i] * HH + h], swt[i], acc);

    g_partial[((size_t)b * 8 + sl) * HH + h] = acc;
}

// Kernel 4: final reduce of 8 partials -> context [B, H]
__global__ __launch_bounds__(256) void ctx_reduce_kernel(float* __restrict__ ctx)
{
    const int b = blockIdx.x;
    const int h = threadIdx.x;
    float s = 0.0f;
#pragma unroll
    for (int c = 0; c < 8; c++)
        s += g_partial[((size_t)b * 8 + c) * HH + h];
    ctx[(size_t)b * HH + h] = s;
}

// ============================================================================
extern "C" void kernel_launch(void* const* d_in, const int* in_sizes, int n_in,
                              void* d_out, int out_size)
{
    const float* X  = (const float*)d_in[0];   // [64,4096,256]
    const float* W1 = (const float*)d_in[1];   // [256,128]
    const float* b1 = (const float*)d_in[2];   // [128]
    const float* W2 = (const float*)d_in[3];   // [128,1]
    const float* b2 = (const float*)d_in[4];   // [1]

    float* out = (float*)d_out;
    float* ctx = out;                 // [64,256]  (tuple elem 0)
    float* wts = out + BB * HH;       // [64,4096] (tuple elem 1)

    cudaFuncSetAttribute(scores_mma_kernel,
                         cudaFuncAttributeMaxDynamicSharedMemorySize, SMEM_BYTES);

    convW_kernel<<<128, 256>>>(W1);
    scores_mma_kernel<<<NTOK / 128, 256, SMEM_BYTES>>>(X, b1, W2, b2);
    entmax_kernel<<<BB, 512>>>(wts);
    ctx_sparse_kernel<<<dim3(BB, 8), 256>>>(X);
    ctx_reduce_kernel<<<BB, 256>>>(ctx);
}

// round 6
// speedup vs baseline: 1.8147x; 1.0066x over previous
#include <cuda_runtime.h>
#include <cuda_bf16.h>
#include <cstdint>

// Problem constants
#define BB 64
#define SS 4096
#define HH 256
#define AA 128
#define NTOK (BB * SS)          // 262144 tokens

#define PADK 72                 // bf16 elems per smem row (144B, conflict-free)

// ---------------- scratch (device globals; no allocation allowed) ----------
__device__ float g_scores[NTOK];                    // [B,S] pre-entmax scores
__device__ float g_partial[BB * 8 * HH];            // context partials
__device__ int   g_nzidx[NTOK];                     // compacted support idx
__device__ float g_nzw[NTOK];                       // compacted support w
__device__ int   g_nzcnt[BB];                       // support count per batch
// W1 pre-converted to bf16 hi/lo, padded chunk layout: [4 chunks][128 n][72]
__device__ __nv_bfloat16 g_Bhi[4 * 128 * PADK];
__device__ __nv_bfloat16 g_Blo[4 * 128 * PADK];

// ---------------- PTX helpers ----------------------------------------------
__device__ __forceinline__ uint32_t s2u(const void* p) {
    uint32_t a;
    asm("{ .reg .u64 t; cvta.to.shared.u64 t, %1; cvt.u32.u64 %0, t; }"
        : "=r"(a) : "l"(p));
    return a;
}

#define LDSM_X4(r0, r1, r2, r3, addr)                                        \
    asm volatile("ldmatrix.sync.aligned.m8n8.x4.shared.b16 {%0,%1,%2,%3}, [%4];" \
                 : "=r"(r0), "=r"(r1), "=r"(r2), "=r"(r3) : "r"(addr))

#define MMA_BF16(d0, d1, d2, d3, a0, a1, a2, a3, b0, b1)                     \
    asm volatile("mma.sync.aligned.m16n8k16.row.col.f32.bf16.bf16.f32 "      \
                 "{%0,%1,%2,%3}, {%4,%5,%6,%7}, {%8,%9}, {%0,%1,%2,%3};"     \
                 : "+f"(d0), "+f"(d1), "+f"(d2), "+f"(d3)                    \
                 : "r"(a0), "r"(a1), "r"(a2), "r"(a3), "r"(b0), "r"(b1))

#define CP_ASYNC16(dst, src)                                                 \
    asm volatile("cp.async.cg.shared.global [%0], [%1], 16;"                 \
                 :: "r"(dst), "l"(src))
#define CP_COMMIT() asm volatile("cp.async.commit_group;" ::: "memory")
#define CP_WAIT0()  asm volatile("cp.async.wait_group 0;" ::: "memory")

// ============================================================================
// Kernel 0: convert W1 [256,128] fp32 -> bf16 hi/lo, padded chunk layout.
// ============================================================================
__global__ __launch_bounds__(256) void convW_kernel(const float* __restrict__ W1)
{
    const int idx = blockIdx.x * 256 + threadIdx.x;   // 0..32767
    const int k = idx >> 7;       // H index 0..255
    const int n = idx & 127;      // A index 0..127
    const float w = W1[idx];
    const __nv_bfloat16 hi = __float2bfloat16(w);
    const float hf = __bfloat162float(hi);
    const __nv_bfloat16 lo = __float2bfloat16(w - hf);
    const int chunk = k >> 6;
    const int kc = k & 63;
    const int pos = (chunk * 128 + n) * PADK + kc;
    g_Bhi[pos] = hi;
    g_Blo[pos] = lo;
}

// ============================================================================
// Kernel 1: scores GEMM via mma.sync bf16 hi/lo split + fused tanh/W2
// epilogue. One CTA per 128 tokens; 8 warps, warp tile m32 x n64 (4x2 grid)
// to cut redundant B ldmatrix traffic. cp.async B tiles, reg-staged A.
// ============================================================================
// dynamic smem byte offsets
#define OFF_AHI   0
#define OFF_ALO   18432
#define OFF_BHI   36864
#define OFF_BLO   55296
#define OFF_B1S   73728
#define OFF_W2S   74240
#define OFF_SRED  74752
#define SMEM_BYTES 75776

__global__ __launch_bounds__(256, 2) void scores_mma_kernel(
    const float* __restrict__ X,    // [NTOK, 256]
    const float* __restrict__ b1,   // [128]
    const float* __restrict__ W2,   // [128]
    const float* __restrict__ b2)   // [1]
{
    extern __shared__ __align__(16) char smem[];
    const uint32_t sb = s2u(smem);
    const int tid = threadIdx.x;
    const int wid = tid >> 5;
    const int lane = tid & 31;
    const int tok0 = blockIdx.x * 128;

    const int wm = (wid >> 1) * 32;   // warp M origin (0,32,64,96)
    const int wn = (wid & 1) * 64;    // warp N origin (0,64)

    if (tid < 128) {
        *(float*)(smem + OFF_B1S + tid * 4) = b1[tid];
        *(float*)(smem + OFF_W2S + tid * 4) = W2[tid];
    }

    // acc[mi][nf8][4]: mi = m16 block (2), nf8 = n8 frag (8)
    float acc[2][8][4];
#pragma unroll
    for (int mi = 0; mi < 2; mi++)
#pragma unroll
        for (int nf = 0; nf < 8; nf++)
#pragma unroll
            for (int i = 0; i < 4; i++) acc[mi][nf][i] = 0.0f;

    const int row  = tid >> 1;      // 0..127 (token row in tile)
    const int half = tid & 1;       // 32-col half of the 64-col chunk
    const float4* Xr = (const float4*)(X + (size_t)(tok0 + row) * HH);
    const uint32_t a_boff = (uint32_t)row * (PADK * 2) + (uint32_t)(half * 64);

    // ldmatrix lane addressing
    const int grp = lane >> 3;            // 0..3
    const uint32_t a_rowl = (uint32_t)((lane & 7) + (grp & 1) * 8); // within m16
    const uint32_t a_kad = (uint32_t)((grp >> 1) * 8) * 2;
    const uint32_t b_rowbase = (uint32_t)((lane & 7) + (grp >> 1) * 8);
    const uint32_t b_kad = (uint32_t)((grp & 1) * 8) * 2;

    // register-staged A prefetch (chunk 0)
    float4 v[8];
#pragma unroll
    for (int q = 0; q < 8; q++) v[q] = Xr[half * 8 + q];

    for (int c = 0; c < 4; c++) {
        // ---- B chunk via cp.async (L2-resident, 18432B each) ----
        {
            const char* srch = (const char*)(g_Bhi + c * 128 * PADK);
            const char* srcl = (const char*)(g_Blo + c * 128 * PADK);
#pragma unroll
            for (int i = 0; i < 5; i++) {
                const int idx = tid + i * 256;
                if (idx < 1152) {
                    CP_ASYNC16(sb + OFF_BHI + idx * 16, srch + idx * 16);
                    CP_ASYNC16(sb + OFF_BLO + idx * 16, srcl + idx * 16);
                }
            }
            CP_COMMIT();
        }
        // ---- convert staged A chunk -> smem hi/lo ----
        {
#pragma unroll
            for (int q = 0; q < 8; q++) {
                const float4 vv = v[q];
                __nv_bfloat162 h0 = __floats2bfloat162_rn(vv.x, vv.y);
                __nv_bfloat162 h1 = __floats2bfloat162_rn(vv.z, vv.w);
                float rx = vv.x - __bfloat162float(__low2bfloat16(h0));
                float ry = vv.y - __bfloat162float(__high2bfloat16(h0));
                float rz = vv.z - __bfloat162float(__low2bfloat16(h1));
                float rw = vv.w - __bfloat162float(__high2bfloat16(h1));
                __nv_bfloat162 l0 = __floats2bfloat162_rn(rx, ry);
                __nv_bfloat162 l1 = __floats2bfloat162_rn(rz, rw);

                const uint32_t boff = a_boff + (uint32_t)(q * 8);
                uint2 hw, lw;
                hw.x = *(uint32_t*)&h0; hw.y = *(uint32_t*)&h1;
                lw.x = *(uint32_t*)&l0; lw.y = *(uint32_t*)&l1;
                *(uint2*)(smem + OFF_AHI + boff) = hw;
                *(uint2*)(smem + OFF_ALO + boff) = lw;
            }
        }
        // ---- prefetch next A chunk into regs (latency hidden by MMAs) ----
        if (c < 3) {
#pragma unroll
            for (int q = 0; q < 8; q++) v[q] = Xr[(c + 1) * 16 + half * 8 + q];
        }
        CP_WAIT0();
        __syncthreads();

        // ---- 4 k-steps of 16 ----
#pragma unroll
        for (int ks = 0; ks < 4; ks++) {
            const uint32_t k0b = (uint32_t)(ks * 16) * 2;
            // A fragments: 2 m16 blocks x (hi,lo)
            uint32_t ah[2][4], al[2][4];
#pragma unroll
            for (int mi = 0; mi < 2; mi++) {
                const uint32_t a_off =
                    ((uint32_t)(wm + mi * 16) + a_rowl) * (PADK * 2) + k0b + a_kad;
                LDSM_X4(ah[mi][0], ah[mi][1], ah[mi][2], ah[mi][3],
                        sb + OFF_AHI + a_off);
                LDSM_X4(al[mi][0], al[mi][1], al[mi][2], al[mi][3],
                        sb + OFF_ALO + a_off);
            }
            // B: 4 n16 groups
#pragma unroll
            for (int ng = 0; ng < 4; ng++) {
                const uint32_t b_off =
                    ((uint32_t)(wn + ng * 16) + b_rowbase) * (PADK * 2) + k0b + b_kad;
                uint32_t bh0, bh1, bh2, bh3, bl0, bl1, bl2, bl3;
                LDSM_X4(bh0, bh1, bh2, bh3, sb + OFF_BHI + b_off);
                LDSM_X4(bl0, bl1, bl2, bl3, sb + OFF_BLO + b_off);
#pragma unroll
                for (int mi = 0; mi < 2; mi++) {
                    float* d0 = acc[mi][ng * 2];
                    float* d1 = acc[mi][ng * 2 + 1];
                    MMA_BF16(d0[0], d0[1], d0[2], d0[3],
                             ah[mi][0], ah[mi][1], ah[mi][2], ah[mi][3], bh0, bh1);
                    MMA_BF16(d0[0], d0[1], d0[2], d0[3],
                             ah[mi][0], ah[mi][1], ah[mi][2], ah[mi][3], bl0, bl1);
                    MMA_BF16(d0[0], d0[1], d0[2], d0[3],
                             al[mi][0], al[mi][1], al[mi][2], al[mi][3], bh0, bh1);
                    MMA_BF16(d1[0], d1[1], d1[2], d1[3],
                             ah[mi][0], ah[mi][1], ah[mi][2], ah[mi][3], bh2, bh3);
                    MMA_BF16(d1[0], d1[1], d1[2], d1[3],
                             ah[mi][0], ah[mi][1], ah[mi][2], ah[mi][3], bl2, bl3);
                    MMA_BF16(d1[0], d1[1], d1[2], d1[3],
                             al[mi][0], al[mi][1], al[mi][2], al[mi][3], bh2, bh3);
                }
            }
        }
        __syncthreads();
    }

    // ---- epilogue: tanh dot W2 over warp's 64 cols, then cross-warp add ----
    float* sred = (float*)(smem + OFF_SRED);   // [2][128]: col-half x row
#pragma unroll
    for (int mi = 0; mi < 2; mi++) {
        float s0 = 0.0f, s1 = 0.0f;
#pragma unroll
        for (int nf = 0; nf < 8; nf++) {
            const int c0 = wn + nf * 8 + (lane & 3) * 2;
            const float bb0 = *(const float*)(smem + OFF_B1S + c0 * 4);
            const float bb1v = *(const float*)(smem + OFF_B1S + (c0 + 1) * 4);
            const float ww0 = *(const float*)(smem + OFF_W2S + c0 * 4);
            const float ww1 = *(const float*)(smem + OFF_W2S + (c0 + 1) * 4);
            s0 += tanhf(acc[mi][nf][0] + bb0) * ww0 +
                  tanhf(acc[mi][nf][1] + bb1v) * ww1;
            s1 += tanhf(acc[mi][nf][2] + bb0) * ww0 +
                  tanhf(acc[mi][nf][3] + bb1v) * ww1;
        }
        s0 += __shfl_xor_sync(0xffffffffu, s0, 1);
        s0 += __shfl_xor_sync(0xffffffffu, s0, 2);
        s1 += __shfl_xor_sync(0xffffffffu, s1, 1);
        s1 += __shfl_xor_sync(0xffffffffu, s1, 2);
        if ((lane & 3) == 0) {
            const int r = wm + mi * 16 + (lane >> 2);
            sred[(wid & 1) * 128 + r]     = s0;
            sred[(wid & 1) * 128 + r + 8] = s1;
        }
    }
    __syncthreads();
    if (tid < 128)
        g_scores[tok0 + tid] = sred[tid] + sred[128 + tid] + b2[0];
}

// ============================================================================
// Kernel 2: exact entmax-1.5 per batch row (S=4096) + deterministic
// compaction of the support set (index order preserved).
// ============================================================================
__global__ __launch_bounds__(512) void entmax_kernel(float* __restrict__ weights)
{
    const int b = blockIdx.x;
    const int tid = threadIdx.x;

    __shared__ float srt[SS];
    __shared__ float tau[SS];
    __shared__ float aux1[512], aux2[512];
    __shared__ float red[512];
    __shared__ int   iscan[512];
    __shared__ float s_bcast[2];

    const float* sc = g_scores + (size_t)b * SS;

    float m = -1e30f;
    for (int i = tid; i < SS; i += 512) {
        float v = 0.5f * sc[i];
        srt[i] = v;
        m = fmaxf(m, v);
    }
    red[tid] = m;
    __syncthreads();
    for (int s = 256; s > 0; s >>= 1) {
        if (tid < s) red[tid] = fmaxf(red[tid], red[tid + s]);
        __syncthreads();
    }
    const float mx = red[0];
    __syncthreads();

    for (int i = tid; i < SS; i += 512)
        srt[i] = mx - srt[i];
    __syncthreads();

    for (int kk = 2; kk <= SS; kk <<= 1) {
        for (int jj = kk >> 1; jj > 0; jj >>= 1) {
            for (int i = tid; i < SS; i += 512) {
                const int l = i ^ jj;
                if (l > i) {
                    const float a = srt[i];
                    const float c = srt[l];
                    const bool up = ((i & kk) == 0);
                    if (up ? (a > c) : (a < c)) { srt[i] = c; srt[l] = a; }
                }
            }
            __syncthreads();
        }
    }

    const int base = tid * 8;
    float l1[8], l2[8];
    {
        float s1 = 0.0f, s2 = 0.0f;
#pragma unroll
        for (int j = 0; j < 8; j++) {
            const float v = -srt[base + j];
            s1 += v; s2 += v * v;
            l1[j] = s1; l2[j] = s2;
        }
        aux1[tid] = s1; aux2[tid] = s2;
    }
    __syncthreads();
    for (int off = 1; off < 512; off <<= 1) {
        float a1 = 0.0f, a2 = 0.0f;
        if (tid >= off) { a1 = aux1[tid - off]; a2 = aux2[tid - off]; }
        __syncthreads();
        aux1[tid] += a1; aux2[tid] += a2;
        __syncthreads();
    }
    const float off1 = aux1[tid] - l1[7];
    const float off2 = aux2[tid] - l2[7];

    float cnt = 0.0f;
#pragma unroll
    for (int j = 0; j < 8; j++) {
        const int k = base + j;
        const float fk = (float)(k + 1);
        const float c1 = off1 + l1[j];
        const float c2 = off2 + l2[j];
        const float mean = c1 / fk;
        const float msq  = c2 / fk;
        const float ssv  = fk * (msq - mean * mean);
        const float delta = fmaxf((1.0f - ssv) / fk, 0.0f);
        const float t = mean - sqrtf(delta);
        tau[k] = t;
        const float zsk = -srt[k];
        if (t <= zsk) cnt += 1.0f;
    }
    red[tid] = cnt;
    __syncthreads();
    for (int s = 256; s > 0; s >>= 1) {
        if (tid < s) red[tid] += red[tid + s];
        __syncthreads();
    }
    if (tid == 0) {
        const int k_star = (int)(red[0] + 0.5f);
        s_bcast[1] = tau[k_star - 1];
    }
    __syncthreads();
    const float tau_star = s_bcast[1];

    // dense weights (contiguous 8 per thread) + support compaction
    float* wout = weights + (size_t)b * SS;
    float wv[8];
    int mycnt = 0;
#pragma unroll
    for (int j = 0; j < 8; j++) {
        const int i = base + j;
        const float v = 0.5f * sc[i] - mx - tau_star;
        const float r = v > 0.0f ? v : 0.0f;
        const float w = r * r;
        wv[j] = w;
        wout[i] = w;
        if (w > 0.0f) mycnt++;
    }
    iscan[tid] = mycnt;
    __syncthreads();
    for (int off = 1; off < 512; off <<= 1) {
        int a = 0;
        if (tid >= off) a = iscan[tid - off];
        __syncthreads();
        iscan[tid] += a;
        __syncthreads();
    }
    int pos = iscan[tid] - mycnt;   // exclusive prefix
#pragma unroll
    for (int j = 0; j < 8; j++) {
        if (wv[j] > 0.0f) {
            g_nzidx[(size_t)b * SS + pos] = base + j;
            g_nzw[(size_t)b * SS + pos]   = wv[j];
            pos++;
        }
    }
    if (tid == 511) g_nzcnt[b] = iscan[511];
}

// ============================================================================
// Kernel 3: sparse context partials.  grid (B, 8), 256 threads (one per h).
// ============================================================================
__global__ __launch_bounds__(256) void ctx_sparse_kernel(const float* __restrict__ X)
{
    const int b = blockIdx.x;
    const int sl = blockIdx.y;
    const int h = threadIdx.x;

    __shared__ int   sidx[512];
    __shared__ float swt[512];

    const int cnt = g_nzcnt[b];
    const int per = (cnt + 7) >> 3;
    const int s0 = sl * per;
    int s1 = s0 + per; if (s1 > cnt) s1 = cnt;
    const int n = s1 - s0;

    for (int t = h; t < n; t += 256) {
        sidx[t] = g_nzidx[(size_t)b * SS + s0 + t];
        swt[t]  = g_nzw[(size_t)b * SS + s0 + t];
    }
    __syncthreads();

    const float* Xb = X + (size_t)b * SS * HH;
    float acc = 0.0f;
    int i = 0;
    for (; i + 4 <= n; i += 4) {
        const float x0 = Xb[(size_t)sidx[i]     * HH + h];
        const float x1 = Xb[(size_t)sidx[i + 1] * HH + h];
        const float x2 = Xb[(size_t)sidx[i + 2] * HH + h];
        const float x3 = Xb[(size_t)sidx[i + 3] * HH + h];
        acc = fmaf(x0, swt[i], acc);
        acc = fmaf(x1, swt[i + 1], acc);
        acc = fmaf(x2, swt[i + 2], acc);
        acc = fmaf(x3, swt[i + 3], acc);
    }
    for (; i < n; i++)
        acc = fmaf(Xb[(size_t)sidx[i] * HH + h], swt[i], acc);

    g_partial[((size_t)b * 8 + sl) * HH + h] = acc;
}

// Kernel 4: final reduce of 8 partials -> context [B, H]
__global__ __launch_bounds__(256) void ctx_reduce_kernel(float* __restrict__ ctx)
{
    const int b = blockIdx.x;
    const int h = threadIdx.x;
    float s = 0.0f;
#pragma unroll
    for (int c = 0; c < 8; c++)
        s += g_partial[((size_t)b * 8 + c) * HH + h];
    ctx[(size_t)b * HH + h] = s;
}

// ============================================================================
extern "C" void kernel_launch(void* const* d_in, const int* in_sizes, int n_in,
                              void* d_out, int out_size)
{
    const float* X  = (const float*)d_in[0];   // [64,4096,256]
    const float* W1 = (const float*)d_in[1];   // [256,128]
    const float* b1 = (const float*)d_in[2];   // [128]
    const float* W2 = (const float*)d_in[3];   // [128,1]
    const float* b2 = (const float*)d_in[4];   // [1]

    float* out = (float*)d_out;
    float* ctx = out;                 // [64,256]  (tuple elem 0)
    float* wts = out + BB * HH;       // [64,4096] (tuple elem 1)

    cudaFuncSetAttribute(scores_mma_kernel,
                         cudaFuncAttributeMaxDynamicSharedMemorySize, SMEM_BYTES);

    convW_kernel<<<128, 256>>>(W1);
    scores_mma_kernel<<<NTOK / 128, 256, SMEM_BYTES>>>(X, b1, W2, b2);
    entmax_kernel<<<BB, 512>>>(wts);
    ctx_sparse_kernel<<<dim3(BB, 8), 256>>>(X);
    ctx_reduce_kernel<<<BB, 256>>>(ctx);
}

// round 7
// speedup vs baseline: 2.1746x; 1.1983x over previous
#include <cuda_runtime.h>
#include <cuda_bf16.h>
#include <cstdint>

// Problem constants
#define BB 64
#define SS 4096
#define HH 256
#define AA 128
#define NTOK (BB * SS)          // 262144 tokens

#define PADK 72                 // bf16 elems per smem row (144B, conflict-free)
#define NPART 16                // context partial slices per batch

// ---------------- scratch (device globals; no allocation allowed) ----------
__device__ float g_scores[NTOK];                    // [B,S] pre-entmax scores
__device__ float g_partial[BB * NPART * HH];        // context partials
__device__ int   g_nzidx[NTOK];                     // compacted support idx
__device__ float g_nzw[NTOK];                       // compacted support w
__device__ int   g_nzcnt[BB];                       // support count per batch
// W1 pre-converted to bf16 hi/lo, padded chunk layout: [4 chunks][128 n][72]
__device__ __nv_bfloat16 g_Bhi[4 * 128 * PADK];
__device__ __nv_bfloat16 g_Blo[4 * 128 * PADK];

// ---------------- PTX helpers ----------------------------------------------
__device__ __forceinline__ uint32_t s2u(const void* p) {
    uint32_t a;
    asm("{ .reg .u64 t; cvta.to.shared.u64 t, %1; cvt.u32.u64 %0, t; }"
        : "=r"(a) : "l"(p));
    return a;
}

#define LDSM_X4(r0, r1, r2, r3, addr)                                        \
    asm volatile("ldmatrix.sync.aligned.m8n8.x4.shared.b16 {%0,%1,%2,%3}, [%4];" \
                 : "=r"(r0), "=r"(r1), "=r"(r2), "=r"(r3) : "r"(addr))

#define MMA_BF16(d0, d1, d2, d3, a0, a1, a2, a3, b0, b1)                     \
    asm volatile("mma.sync.aligned.m16n8k16.row.col.f32.bf16.bf16.f32 "      \
                 "{%0,%1,%2,%3}, {%4,%5,%6,%7}, {%8,%9}, {%0,%1,%2,%3};"     \
                 : "+f"(d0), "+f"(d1), "+f"(d2), "+f"(d3)                    \
                 : "r"(a0), "r"(a1), "r"(a2), "r"(a3), "r"(b0), "r"(b1))

#define CP_ASYNC16(dst, src)                                                 \
    asm volatile("cp.async.cg.shared.global [%0], [%1], 16;"                 \
                 :: "r"(dst), "l"(src))
#define CP_COMMIT() asm volatile("cp.async.commit_group;" ::: "memory")
#define CP_WAIT0()  asm volatile("cp.async.wait_group 0;" ::: "memory")

// ============================================================================
// Kernel 0: convert W1 [256,128] fp32 -> bf16 hi/lo, padded chunk layout.
// ============================================================================
__global__ __launch_bounds__(256) void convW_kernel(const float* __restrict__ W1)
{
    const int idx = blockIdx.x * 256 + threadIdx.x;   // 0..32767
    const int k = idx >> 7;       // H index 0..255
    const int n = idx & 127;      // A index 0..127
    const float w = W1[idx];
    const __nv_bfloat16 hi = __float2bfloat16(w);
    const float hf = __bfloat162float(hi);
    const __nv_bfloat16 lo = __float2bfloat16(w - hf);
    const int chunk = k >> 6;
    const int kc = k & 63;
    const int pos = (chunk * 128 + n) * PADK + kc;
    g_Bhi[pos] = hi;
    g_Blo[pos] = lo;
}

// ============================================================================
// Kernel 1: scores GEMM via mma.sync bf16 hi/lo split + fused tanh/W2
// epilogue. One CTA per 128 tokens; 8 warps, warp tile m32 x n64.
// ============================================================================
// dynamic smem byte offsets
#define OFF_AHI   0
#define OFF_ALO   18432
#define OFF_BHI   36864
#define OFF_BLO   55296
#define OFF_B1S   73728
#define OFF_W2S   74240
#define OFF_SRED  74752
#define SMEM_BYTES 75776

__global__ __launch_bounds__(256, 2) void scores_mma_kernel(
    const float* __restrict__ X,    // [NTOK, 256]
    const float* __restrict__ b1,   // [128]
    const float* __restrict__ W2,   // [128]
    const float* __restrict__ b2)   // [1]
{
    extern __shared__ __align__(16) char smem[];
    const uint32_t sb = s2u(smem);
    const int tid = threadIdx.x;
    const int wid = tid >> 5;
    const int lane = tid & 31;
    const int tok0 = blockIdx.x * 128;

    const int wm = (wid >> 1) * 32;   // warp M origin (0,32,64,96)
    const int wn = (wid & 1) * 64;    // warp N origin (0,64)

    if (tid < 128) {
        *(float*)(smem + OFF_B1S + tid * 4) = b1[tid];
        *(float*)(smem + OFF_W2S + tid * 4) = W2[tid];
    }

    float acc[2][8][4];
#pragma unroll
    for (int mi = 0; mi < 2; mi++)
#pragma unroll
        for (int nf = 0; nf < 8; nf++)
#pragma unroll
            for (int i = 0; i < 4; i++) acc[mi][nf][i] = 0.0f;

    const int row  = tid >> 1;      // 0..127 (token row in tile)
    const int half = tid & 1;       // 32-col half of the 64-col chunk
    const float4* Xr = (const float4*)(X + (size_t)(tok0 + row) * HH);
    const uint32_t a_boff = (uint32_t)row * (PADK * 2) + (uint32_t)(half * 64);

    const int grp = lane >> 3;
    const uint32_t a_rowl = (uint32_t)((lane & 7) + (grp & 1) * 8);
    const uint32_t a_kad = (uint32_t)((grp >> 1) * 8) * 2;
    const uint32_t b_rowbase = (uint32_t)((lane & 7) + (grp >> 1) * 8);
    const uint32_t b_kad = (uint32_t)((grp & 1) * 8) * 2;

    float4 v[8];
#pragma unroll
    for (int q = 0; q < 8; q++) v[q] = Xr[half * 8 + q];

    for (int c = 0; c < 4; c++) {
        {
            const char* srch = (const char*)(g_Bhi + c * 128 * PADK);
            const char* srcl = (const char*)(g_Blo + c * 128 * PADK);
#pragma unroll
            for (int i = 0; i < 5; i++) {
                const int idx = tid + i * 256;
                if (idx < 1152) {
                    CP_ASYNC16(sb + OFF_BHI + idx * 16, srch + idx * 16);
                    CP_ASYNC16(sb + OFF_BLO + idx * 16, srcl + idx * 16);
                }
            }
            CP_COMMIT();
        }
        {
#pragma unroll
            for (int q = 0; q < 8; q++) {
                const float4 vv = v[q];
                __nv_bfloat162 h0 = __floats2bfloat162_rn(vv.x, vv.y);
                __nv_bfloat162 h1 = __floats2bfloat162_rn(vv.z, vv.w);
                float rx = vv.x - __bfloat162float(__low2bfloat16(h0));
                float ry = vv.y - __bfloat162float(__high2bfloat16(h0));
                float rz = vv.z - __bfloat162float(__low2bfloat16(h1));
                float rw = vv.w - __bfloat162float(__high2bfloat16(h1));
                __nv_bfloat162 l0 = __floats2bfloat162_rn(rx, ry);
                __nv_bfloat162 l1 = __floats2bfloat162_rn(rz, rw);

                const uint32_t boff = a_boff + (uint32_t)(q * 8);
                uint2 hw, lw;
                hw.x = *(uint32_t*)&h0; hw.y = *(uint32_t*)&h1;
                lw.x = *(uint32_t*)&l0; lw.y = *(uint32_t*)&l1;
                *(uint2*)(smem + OFF_AHI + boff) = hw;
                *(uint2*)(smem + OFF_ALO + boff) = lw;
            }
        }
        if (c < 3) {
#pragma unroll
            for (int q = 0; q < 8; q++) v[q] = Xr[(c + 1) * 16 + half * 8 + q];
        }
        CP_WAIT0();
        __syncthreads();

#pragma unroll
        for (int ks = 0; ks < 4; ks++) {
            const uint32_t k0b = (uint32_t)(ks * 16) * 2;
            uint32_t ah[2][4], al[2][4];
#pragma unroll
            for (int mi = 0; mi < 2; mi++) {
                const uint32_t a_off =
                    ((uint32_t)(wm + mi * 16) + a_rowl) * (PADK * 2) + k0b + a_kad;
                LDSM_X4(ah[mi][0], ah[mi][1], ah[mi][2], ah[mi][3],
                        sb + OFF_AHI + a_off);
                LDSM_X4(al[mi][0], al[mi][1], al[mi][2], al[mi][3],
                        sb + OFF_ALO + a_off);
            }
#pragma unroll
            for (int ng = 0; ng < 4; ng++) {
                const uint32_t b_off =
                    ((uint32_t)(wn + ng * 16) + b_rowbase) * (PADK * 2) + k0b + b_kad;
                uint32_t bh0, bh1, bh2, bh3, bl0, bl1, bl2, bl3;
                LDSM_X4(bh0, bh1, bh2, bh3, sb + OFF_BHI + b_off);
                LDSM_X4(bl0, bl1, bl2, bl3, sb + OFF_BLO + b_off);
#pragma unroll
                for (int mi = 0; mi < 2; mi++) {
                    float* d0 = acc[mi][ng * 2];
                    float* d1 = acc[mi][ng * 2 + 1];
                    MMA_BF16(d0[0], d0[1], d0[2], d0[3],
                             ah[mi][0], ah[mi][1], ah[mi][2], ah[mi][3], bh0, bh1);
                    MMA_BF16(d0[0], d0[1], d0[2], d0[3],
                             ah[mi][0], ah[mi][1], ah[mi][2], ah[mi][3], bl0, bl1);
                    MMA_BF16(d0[0], d0[1], d0[2], d0[3],
                             al[mi][0], al[mi][1], al[mi][2], al[mi][3], bh0, bh1);
                    MMA_BF16(d1[0], d1[1], d1[2], d1[3],
                             ah[mi][0], ah[mi][1], ah[mi][2], ah[mi][3], bh2, bh3);
                    MMA_BF16(d1[0], d1[1], d1[2], d1[3],
                             ah[mi][0], ah[mi][1], ah[mi][2], ah[mi][3], bl2, bl3);
                    MMA_BF16(d1[0], d1[1], d1[2], d1[3],
                             al[mi][0], al[mi][1], al[mi][2], al[mi][3], bh2, bh3);
                }
            }
        }
        __syncthreads();
    }

    // ---- epilogue: tanh dot W2 over warp's 64 cols, then cross-warp add ----
    float* sred = (float*)(smem + OFF_SRED);   // [2][128]
#pragma unroll
    for (int mi = 0; mi < 2; mi++) {
        float s0 = 0.0f, s1 = 0.0f;
#pragma unroll
        for (int nf = 0; nf < 8; nf++) {
            const int c0 = wn + nf * 8 + (lane & 3) * 2;
            const float bb0 = *(const float*)(smem + OFF_B1S + c0 * 4);
            const float bb1v = *(const float*)(smem + OFF_B1S + (c0 + 1) * 4);
            const float ww0 = *(const float*)(smem + OFF_W2S + c0 * 4);
            const float ww1 = *(const float*)(smem + OFF_W2S + (c0 + 1) * 4);
            s0 += tanhf(acc[mi][nf][0] + bb0) * ww0 +
                  tanhf(acc[mi][nf][1] + bb1v) * ww1;
            s1 += tanhf(acc[mi][nf][2] + bb0) * ww0 +
                  tanhf(acc[mi][nf][3] + bb1v) * ww1;
        }
        s0 += __shfl_xor_sync(0xffffffffu, s0, 1);
        s0 += __shfl_xor_sync(0xffffffffu, s0, 2);
        s1 += __shfl_xor_sync(0xffffffffu, s1, 1);
        s1 += __shfl_xor_sync(0xffffffffu, s1, 2);
        if ((lane & 3) == 0) {
            const int r = wm + mi * 16 + (lane >> 2);
            sred[(wid & 1) * 128 + r]     = s0;
            sred[(wid & 1) * 128 + r + 8] = s1;
        }
    }
    __syncthreads();
    if (tid < 128)
        g_scores[tok0 + tid] = sred[tid] + sred[128 + tid] + b2[0];
}

// ============================================================================
// Kernel 2: entmax-1.5 per batch row via fixed-count bisection on
//   f(tau) = sum((z - tau)_+^2) - 1   (monotone; root in [zmax-1, zmax]).
// No sort. z kept in registers (8 per thread). Deterministic.
// ============================================================================
__global__ __launch_bounds__(512) void entmax_kernel(float* __restrict__ weights)
{
    const int b = blockIdx.x;
    const int tid = threadIdx.x;
    const int wid = tid >> 5;
    const int lane = tid & 31;

    __shared__ float red[16];
    __shared__ float s_bc;
    __shared__ int iscan[512];

    const float* sc = g_scores + (size_t)b * SS;
    const int base = tid * 8;

    // load 8 contiguous scores, z = score/2
    float z[8];
    {
        const float4 p0 = ((const float4*)sc)[tid * 2];
        const float4 p1 = ((const float4*)sc)[tid * 2 + 1];
        z[0] = 0.5f * p0.x; z[1] = 0.5f * p0.y;
        z[2] = 0.5f * p0.z; z[3] = 0.5f * p0.w;
        z[4] = 0.5f * p1.x; z[5] = 0.5f * p1.y;
        z[6] = 0.5f * p1.z; z[7] = 0.5f * p1.w;
    }

    // block max
    float m = z[0];
#pragma unroll
    for (int j = 1; j < 8; j++) m = fmaxf(m, z[j]);
#pragma unroll
    for (int o = 16; o > 0; o >>= 1) m = fmaxf(m, __shfl_xor_sync(0xffffffffu, m, o));
    if (lane == 0) red[wid] = m;
    __syncthreads();
    if (tid == 0) {
        float t = red[0];
#pragma unroll
        for (int i = 1; i < 16; i++) t = fmaxf(t, red[i]);
        s_bc = t;
    }
    __syncthreads();
    const float mx = s_bc;
#pragma unroll
    for (int j = 0; j < 8; j++) z[j] -= mx;   // now zmax = 0, root in [-1, 0]

    // bisection (fixed 30 iterations -> tau to ~1e-9)
    float lo = -1.0f, hi = 0.0f;
    for (int it = 0; it < 30; it++) {
        const float mid = 0.5f * (lo + hi);
        float s = 0.0f;
#pragma unroll
        for (int j = 0; j < 8; j++) {
            float d = z[j] - mid;
            d = d > 0.0f ? d : 0.0f;
            s = fmaf(d, d, s);
        }
#pragma unroll
        for (int o = 16; o > 0; o >>= 1) s += __shfl_xor_sync(0xffffffffu, s, o);
        if (lane == 0) red[wid] = s;
        __syncthreads();
        float tot = 0.0f;
#pragma unroll
        for (int i = 0; i < 16; i++) tot += red[i];
        __syncthreads();
        if (tot >= 1.0f) lo = mid; else hi = mid;
    }
    const float tau = 0.5f * (lo + hi);

    // weights + deterministic compaction (index order preserved)
    float* wout = weights + (size_t)b * SS;
    float wv[8];
    int mycnt = 0;
#pragma unroll
    for (int j = 0; j < 8; j++) {
        float d = z[j] - tau;
        d = d > 0.0f ? d : 0.0f;
        const float w = d * d;
        wv[j] = w;
        wout[base + j] = w;
        if (w > 0.0f) mycnt++;
    }
    iscan[tid] = mycnt;
    __syncthreads();
    for (int off = 1; off < 512; off <<= 1) {
        int a = 0;
        if (tid >= off) a = iscan[tid - off];
        __syncthreads();
        iscan[tid] += a;
        __syncthreads();
    }
    int pos = iscan[tid] - mycnt;
#pragma unroll
    for (int j = 0; j < 8; j++) {
        if (wv[j] > 0.0f) {
            g_nzidx[(size_t)b * SS + pos] = base + j;
            g_nzw[(size_t)b * SS + pos]   = wv[j];
            pos++;
        }
    }
    if (tid == 511) g_nzcnt[b] = iscan[511];
}

// ============================================================================
// Kernel 3: sparse context partials.  grid (B, NPART), 256 threads.
// ============================================================================
__global__ __launch_bounds__(256) void ctx_sparse_kernel(const float* __restrict__ X)
{
    const int b = blockIdx.x;
    const int sl = blockIdx.y;
    const int h = threadIdx.x;

    __shared__ int   sidx[320];
    __shared__ float swt[320];

    const int cnt = g_nzcnt[b];
    const int per = (cnt + NPART - 1) / NPART;
    const int s0 = sl * per;
    int s1 = s0 + per; if (s1 > cnt) s1 = cnt;
    const int n = s1 - s0;

    for (int t = h; t < n; t += 256) {
        sidx[t] = g_nzidx[(size_t)b * SS + s0 + t];
        swt[t]  = g_nzw[(size_t)b * SS + s0 + t];
    }
    __syncthreads();

    const float* Xb = X + (size_t)b * SS * HH;
    float acc = 0.0f;
    int i = 0;
    for (; i + 4 <= n; i += 4) {
        const float x0 = Xb[(size_t)sidx[i]     * HH + h];
        const float x1 = Xb[(size_t)sidx[i + 1] * HH + h];
        const float x2 = Xb[(size_t)sidx[i + 2] * HH + h];
        const float x3 = Xb[(size_t)sidx[i + 3] * HH + h];
        acc = fmaf(x0, swt[i], acc);
        acc = fmaf(x1, swt[i + 1], acc);
        acc = fmaf(x2, swt[i + 2], acc);
        acc = fmaf(x3, swt[i + 3], acc);
    }
    for (; i < n; i++)
        acc = fmaf(Xb[(size_t)sidx[i] * HH + h], swt[i], acc);

    g_partial[((size_t)b * NPART + sl) * HH + h] = acc;
}

// Kernel 4: final reduce of NPART partials -> context [B, H]
__global__ __launch_bounds__(256) void ctx_reduce_kernel(float* __restrict__ ctx)
{
    const int b = blockIdx.x;
    const int h = threadIdx.x;
    float s = 0.0f;
#pragma unroll
    for (int c = 0; c < NPART; c++)
        s += g_partial[((size_t)b * NPART + c) * HH + h];
    ctx[(size_t)b * HH + h] = s;
}

// ============================================================================
extern "C" void kernel_launch(void* const* d_in, const int* in_sizes, int n_in,
                              void* d_out, int out_size)
{
    const float* X  = (const float*)d_in[0];   // [64,4096,256]
    const float* W1 = (const float*)d_in[1];   // [256,128]
    const float* b1 = (const float*)d_in[2];   // [128]
    const float* W2 = (const float*)d_in[3];   // [128,1]
    const float* b2 = (const float*)d_in[4];   // [1]

    float* out = (float*)d_out;
    float* ctx = out;                 // [64,256]  (tuple elem 0)
    float* wts = out + BB * HH;       // [64,4096] (tuple elem 1)

    cudaFuncSetAttribute(scores_mma_kernel,
                         cudaFuncAttributeMaxDynamicSharedMemorySize, SMEM_BYTES);

    convW_kernel<<<128, 256>>>(W1);
    scores_mma_kernel<<<NTOK / 128, 256, SMEM_BYTES>>>(X, b1, W2, b2);
    entmax_kernel<<<BB, 512>>>(wts);
    ctx_sparse_kernel<<<dim3(BB, NPART), 256>>>(X);
    ctx_reduce_kernel<<<BB, 256>>>(ctx);
}